// round 10
// baseline (speedup 1.0000x reference)
#include <cuda_runtime.h>
#include <cuda.h>
#include <cstdint>

#define BB   2
#define NN   4096
#define DD   256
#define PC   320     // 3*64 (Wk) + 128 (W_lin)
#define DOUT 64

// ---------------- scratch ---------------------------------------------------
__device__ float g_Kb[(size_t)BB * NN * NN];
__device__ float g_Kw[(size_t)BB * NN * NN];
__device__ float g_sq[BB * NN];
__device__ float g_Wcat[DD * PC];                 // tf32-rounded
__device__ float g_Xt[(size_t)BB * NN * DD];      // tf32-rounded x
__device__ float g_P[(size_t)BB * NN * PC];       // fp32 x@Wcat
__device__ float g_H2r[(size_t)BB * NN * DOUT];   // tf32-rounded h2
__device__ float g_t[(size_t)2 * BB * NN * DOUT]; // tf32-rounded stage-1 result
__device__ float g_t0[(size_t)2 * BB * NN * DOUT];
__device__ float g_t1[(size_t)2 * BB * NN * DOUT];
__device__ float g_t2[(size_t)2 * BB * NN * DOUT];
__device__ float g_t3[(size_t)2 * BB * NN * DOUT];
__device__ float g_g0[(size_t)2 * BB * NN * DOUT];
__device__ float g_g1[(size_t)2 * BB * NN * DOUT];
__device__ float g_g2[(size_t)2 * BB * NN * DOUT];
__device__ float g_g3[(size_t)2 * BB * NN * DOUT];

// ---------------- helpers ---------------------------------------------------
__device__ __forceinline__ uint32_t f2tf(float f) {
    uint32_t u;
    asm volatile("cvt.rna.tf32.f32 %0, %1;" : "=r"(u) : "f"(f));
    return u;
}

__device__ __forceinline__ void mma_tf32(float c[4], const uint32_t a[4], const uint32_t b[2]) {
    asm volatile(
        "mma.sync.aligned.m16n8k8.row.col.f32.tf32.tf32.f32 "
        "{%0,%1,%2,%3}, {%4,%5,%6,%7}, {%8,%9}, {%0,%1,%2,%3};\n"
        : "+f"(c[0]), "+f"(c[1]), "+f"(c[2]), "+f"(c[3])
        : "r"(a[0]), "r"(a[1]), "r"(a[2]), "r"(a[3]),
          "r"(b[0]), "r"(b[1]));
}

__device__ __forceinline__ void cpa16(uint32_t dst, const float* src) {
    asm volatile("cp.async.cg.shared.global [%0], [%1], 16;\n" :: "r"(dst), "l"(src));
}
#define CP_COMMIT() asm volatile("cp.async.commit_group;\n" ::: "memory")
#define CP_WAIT1()  asm volatile("cp.async.wait_group 1;\n" ::: "memory")

// mbarrier + TMA primitives
__device__ __forceinline__ void mbar_init(uint32_t addr, uint32_t cnt) {
    asm volatile("mbarrier.init.shared.b64 [%0], %1;" :: "r"(addr), "r"(cnt) : "memory");
}
__device__ __forceinline__ void mbar_expect(uint32_t addr, uint32_t bytes) {
    asm volatile("mbarrier.arrive.expect_tx.shared.b64 _, [%0], %1;"
                 :: "r"(addr), "r"(bytes) : "memory");
}
__device__ __forceinline__ void mbar_wait(uint32_t addr, uint32_t parity) {
    uint32_t done;
    asm volatile(
        "{\n\t.reg .pred p;\n\t"
        "mbarrier.try_wait.parity.acquire.cta.shared::cta.b64 p, [%1], %2;\n\t"
        "selp.b32 %0, 1, 0, p;\n\t}"
        : "=r"(done) : "r"(addr), "r"(parity) : "memory");
    if (!done) {
        asm volatile(
            "{\n\t.reg .pred P1;\n\t"
            "W_%=:\n\t"
            "mbarrier.try_wait.parity.acquire.cta.shared::cta.b64 P1, [%0], %1, 0x989680;\n\t"
            "@P1 bra.uni D_%=;\n\t"
            "bra.uni W_%=;\n\t"
            "D_%=:\n\t}"
            :: "r"(addr), "r"(parity) : "memory");
    }
}
__device__ __forceinline__ void tma3d(uint32_t smem, const CUtensorMap* map,
                                      int x, int y, int z, uint32_t mbar) {
    asm volatile(
        "cp.async.bulk.tensor.3d.shared::cta.global.tile.mbarrier::complete_tx::bytes "
        "[%0], [%1, {%2, %3, %4}], [%5];"
        :: "r"(smem), "l"(map), "r"(x), "r"(y), "r"(z), "r"(mbar) : "memory");
}

// Closed-form cubic B-spline on uniform knots {0,.25,.5,.75,1} (== reference).
__device__ __forceinline__ float b3fold(float v) {
    float outer = v * v * v * (1.f / 6.f);
    float inner = (((-3.f * v + 12.f) * v - 12.f) * v + 4.f) * (1.f / 6.f);
    return (v < 1.f) ? outer : inner;
}
__device__ __forceinline__ float bk_eval(float t) {
    float v = 2.f - fabsf(4.f * t - 2.f);
    return b3fold(v);
}
__device__ __forceinline__ float wk_eval(float t) {
    float sg = 8.f * t;
    bool lo = (sg < 4.f);
    float sp = lo ? sg : sg - 4.f;
    float v = 2.f - fabsf(sp - 2.f);
    float r = b3fold(v);
    return lo ? r : -r;
}

// ---------------- tiny prep kernels -----------------------------------------
__global__ void k_xcvt(const float* __restrict__ x) {
    int i = blockIdx.x * 256 + threadIdx.x;
    float4 v = ((const float4*)x)[i];
    uint4 o;
    o.x = f2tf(v.x); o.y = f2tf(v.y); o.z = f2tf(v.z); o.w = f2tf(v.w);
    ((uint4*)g_Xt)[i] = o;
}

__global__ void k_sqnorm(const float* __restrict__ x) {
    int row  = blockIdx.x * 8 + (threadIdx.x >> 5);
    int lane = threadIdx.x & 31;
    const float* xr = x + (size_t)row * DD;
    float s = 0.f;
    #pragma unroll
    for (int i = lane; i < DD; i += 32) { float v = xr[i]; s += v * v; }
    #pragma unroll
    for (int o = 16; o; o >>= 1) s += __shfl_xor_sync(0xffffffffu, s, o);
    if (lane == 0) g_sq[row] = s;
}

__global__ void k_wcat(const float* __restrict__ Wk, const float* __restrict__ Wl) {
    int i = blockIdx.x * 256 + threadIdx.x;
    if (i >= DD * PC) return;
    int d = i / PC, cidx = i % PC;
    float v;
    if (cidx < 192) v = Wk[(size_t)(cidx / 64) * DD * 64 + (size_t)d * 64 + (cidx & 63)];
    else            v = Wl[(size_t)d * 128 + (cidx - 192)];
    g_Wcat[i] = __uint_as_float(f2tf(v));
}

// ---------------- kernel: Gram + spline (R9, unchanged) ----------------------
__global__ __launch_bounds__(256, 4) void k_gram() {
    __shared__ float sm[2 * 3840];
    int h   = blockIdx.x & 1;
    int idx = blockIdx.x >> 1;
    int b   = blockIdx.y;
    int tj = (int)((sqrtf(8.f * idx + 1.f) - 1.f) * 0.5f);
    while ((tj + 1) * (tj + 2) / 2 <= idx) ++tj;
    while (tj * (tj + 1) / 2 > idx) --tj;
    int ti = idx - tj * (tj + 1) / 2;

    int tid = threadIdx.x, lane = tid & 31, wid = tid >> 5;
    int wm = wid & 3, wn = wid >> 2;
    const float* Xa = g_Xt + ((size_t)b * NN + (size_t)ti * 128) * DD;
    const float* Xb = g_Xt + ((size_t)b * NN + (size_t)tj * 128 + (size_t)h * 64) * DD;
    uint32_t sb = (uint32_t)__cvta_generic_to_shared(sm);

    float c[2][4][4];
    #pragma unroll
    for (int i = 0; i < 2; i++)
        #pragma unroll
        for (int j = 0; j < 4; j++)
            #pragma unroll
            for (int r = 0; r < 4; r++) c[i][j][r] = 0.f;

    int arow_l = tid >> 2,         apart_l = (tid & 3) << 2;
    int arow_h = (256 + tid) >> 2, apart_h = ((256 + tid) & 3) << 2;
    int brow   = tid >> 2,         bpart   = (tid & 3) << 2;

    {
        uint32_t sA = sb, sB = sb + 2560 * 4;
        cpa16(sA + (arow_l * 20 + apart_l) * 4, Xa + (size_t)arow_l * DD + apart_l);
        cpa16(sA + (arow_h * 20 + apart_h) * 4, Xa + (size_t)arow_h * DD + apart_h);
        cpa16(sB + (brow * 20 + bpart) * 4, Xb + (size_t)brow * DD + bpart);
    }
    CP_COMMIT();

    for (int cc = 0; cc < 16; ++cc) {
        if (cc + 1 < 16) {
            int s = (cc + 1) & 1, k0 = (cc + 1) * 16;
            uint32_t sA = sb + (s * 3840) * 4, sB = sA + 2560 * 4;
            cpa16(sA + (arow_l * 20 + apart_l) * 4, Xa + (size_t)arow_l * DD + k0 + apart_l);
            cpa16(sA + (arow_h * 20 + apart_h) * 4, Xa + (size_t)arow_h * DD + k0 + apart_h);
            cpa16(sB + (brow * 20 + bpart) * 4, Xb + (size_t)brow * DD + k0 + bpart);
        }
        CP_COMMIT();
        CP_WAIT1();
        __syncthreads();
        const float* A  = sm + (cc & 1) * 3840;
        const float* Bp = A + 2560;
        #pragma unroll
        for (int ks = 0; ks < 2; ++ks) {
            int kk = ks * 8 + (lane & 3);
            uint32_t a[2][4], bf[4][2];
            #pragma unroll
            for (int mi = 0; mi < 2; mi++) {
                int mr = wm * 32 + mi * 16 + (lane >> 2);
                a[mi][0] = __float_as_uint(A[mr * 20 + kk]);
                a[mi][1] = __float_as_uint(A[(mr + 8) * 20 + kk]);
                a[mi][2] = __float_as_uint(A[mr * 20 + kk + 4]);
                a[mi][3] = __float_as_uint(A[(mr + 8) * 20 + kk + 4]);
            }
            #pragma unroll
            for (int ni = 0; ni < 4; ni++) {
                int nc = wn * 32 + ni * 8 + (lane >> 2);
                bf[ni][0] = __float_as_uint(Bp[nc * 20 + kk]);
                bf[ni][1] = __float_as_uint(Bp[nc * 20 + kk + 4]);
            }
            #pragma unroll
            for (int mi = 0; mi < 2; mi++)
                #pragma unroll
                for (int ni = 0; ni < 4; ni++)
                    mma_tf32(c[mi][ni], a[mi], bf[ni]);
        }
        __syncthreads();
    }

    float* Kb = g_Kb + (size_t)b * NN * NN;
    float* Kw = g_Kw + (size_t)b * NN * NN;
    const float* sq = g_sq + b * NN;
    int i0 = ti * 128 + wm * 32, j0 = tj * 128 + h * 64 + wn * 32;
    bool mir = (ti != tj);
    #pragma unroll
    for (int mi = 0; mi < 2; mi++)
        #pragma unroll
        for (int ni = 0; ni < 4; ni++)
            #pragma unroll
            for (int r = 0; r < 4; r++) {
                int i = i0 + mi * 16 + (lane >> 2) + ((r >> 1) << 3);
                int j = j0 + ni * 8 + ((lane & 3) << 1) + (r & 1);
                float d2 = sq[i] + sq[j] - 2.f * c[mi][ni][r];
                d2 = fmaxf(d2, 0.f);
                float t = __expf(d2 * (-1.f / 512.f));
                float bk = __uint_as_float(f2tf(bk_eval(t)));
                float wk = __uint_as_float(f2tf(wk_eval(t)));
                Kb[(size_t)i * NN + j] = bk;
                Kw[(size_t)i * NN + j] = wk;
                if (mir) {
                    Kb[(size_t)j * NN + i] = bk;
                    Kw[(size_t)j * NN + i] = wk;
                }
            }
}

// ---------------- kernel: projection P = x @ Wcat (unchanged) ----------------
__global__ __launch_bounds__(256) void k_proj() {
    __shared__ float sm[2 * 3648];
    int c0 = blockIdx.x * 64, byr = blockIdx.y;
    int tid = threadIdx.x, lane = tid & 31, wid = tid >> 5;
    int wm = wid & 1, wn = wid >> 1;
    const float* Xa = g_Xt + (size_t)byr * 128 * DD;
    uint32_t sb = (uint32_t)__cvta_generic_to_shared(sm);

    float c[4][2][4];
    #pragma unroll
    for (int i = 0; i < 4; i++)
        #pragma unroll
        for (int j = 0; j < 2; j++)
            #pragma unroll
            for (int r = 0; r < 4; r++) c[i][j][r] = 0.f;

    {
        uint32_t sA = sb, sB = sb + 2560 * 4;
        #pragma unroll
        for (int it = 0; it < 2; ++it) {
            int id = it * 256 + tid;
            int row = id >> 2, part = (id & 3) << 2;
            cpa16(sA + (row * 20 + part) * 4, Xa + (size_t)row * DD + part);
        }
        int kk = tid >> 4, cq = (tid & 15) << 2;
        cpa16(sB + (kk * 68 + cq) * 4, g_Wcat + (size_t)kk * PC + c0 + cq);
    }
    CP_COMMIT();

    for (int cc = 0; cc < 16; ++cc) {
        if (cc + 1 < 16) {
            int s = (cc + 1) & 1, k0 = (cc + 1) * 16;
            uint32_t sA = sb + (s * 3648) * 4, sB = sA + 2560 * 4;
            #pragma unroll
            for (int it = 0; it < 2; ++it) {
                int id = it * 256 + tid;
                int row = id >> 2, part = (id & 3) << 2;
                cpa16(sA + (row * 20 + part) * 4, Xa + (size_t)row * DD + k0 + part);
            }
            int kk = tid >> 4, cq = (tid & 15) << 2;
            cpa16(sB + (kk * 68 + cq) * 4, g_Wcat + (size_t)(k0 + kk) * PC + c0 + cq);
        }
        CP_COMMIT();
        CP_WAIT1();
        __syncthreads();
        const float* A  = sm + (cc & 1) * 3648;
        const float* Bp = A + 2560;
        #pragma unroll
        for (int ks = 0; ks < 2; ++ks) {
            int kk = ks * 8 + (lane & 3);
            uint32_t a[4][4], bf[2][2];
            #pragma unroll
            for (int mi = 0; mi < 4; mi++) {
                int mr = wm * 64 + mi * 16 + (lane >> 2);
                a[mi][0] = __float_as_uint(A[mr * 20 + kk]);
                a[mi][1] = __float_as_uint(A[(mr + 8) * 20 + kk]);
                a[mi][2] = __float_as_uint(A[mr * 20 + kk + 4]);
                a[mi][3] = __float_as_uint(A[(mr + 8) * 20 + kk + 4]);
            }
            #pragma unroll
            for (int ni = 0; ni < 2; ni++) {
                int nc = wn * 16 + ni * 8 + (lane >> 2);
                bf[ni][0] = __float_as_uint(Bp[kk * 68 + nc]);
                bf[ni][1] = __float_as_uint(Bp[(kk + 4) * 68 + nc]);
            }
            #pragma unroll
            for (int mi = 0; mi < 4; mi++)
                #pragma unroll
                for (int ni = 0; ni < 2; ni++)
                    mma_tf32(c[mi][ni], a[mi], bf[ni]);
        }
        __syncthreads();
    }

    #pragma unroll
    for (int mi = 0; mi < 4; mi++)
        #pragma unroll
        for (int ni = 0; ni < 2; ni++)
            #pragma unroll
            for (int r = 0; r < 4; r++) {
                int row = byr * 128 + wm * 64 + mi * 16 + (lane >> 2) + ((r >> 1) << 3);
                int col = c0 + wn * 16 + ni * 8 + ((lane & 3) << 1) + (r & 1);
                float v = c[mi][ni][r];
                g_P[(size_t)row * PC + col] = v;
                if (col >= 128 && col < 192)
                    g_H2r[(size_t)row * DOUT + (col - 128)] = __uint_as_float(f2tf(v));
            }
}

// ---------------- kernel: SpMM partial via TMA -------------------------------
// 64x64 tile, split-K x4, KC=32. 2-stage TMA double buffer.
// A tile: 64x32 f32, SW128 swizzled. B tile: 32x64 f32, unswizzled.
__global__ __launch_bounds__(256, 4) void k_spmm_tma(
    int stage,
    const __grid_constant__ CUtensorMap mKb,
    const __grid_constant__ CUtensorMap mKw,
    const __grid_constant__ CUtensorMap mH1,
    const __grid_constant__ CUtensorMap mH2)
{
    __shared__ __align__(1024) char smt[2][16384];   // per stage: A 8KB | B 8KB
    __shared__ uint64_t mbar[2];
    int rt = blockIdx.x, b = blockIdx.y;
    int type = blockIdx.z >> 2, sp = blockIdx.z & 3;
    int mbase = sp * (NN / 4);
    float* Out;
    if (stage == 1) {
        float* o4[4] = {g_t0, g_t1, g_t2, g_t3};
        Out = o4[sp] + ((size_t)type * BB + b) * NN * DOUT;
    } else {
        float* o4[4] = {g_g0, g_g1, g_g2, g_g3};
        Out = o4[sp] + ((size_t)type * BB + b) * NN * DOUT;
    }
    const CUtensorMap* mK = type ? &mKw : &mKb;
    const CUtensorMap* mH = (stage == 1) ? &mH1 : &mH2;
    int zH = (stage == 1) ? b : (type * BB + b);

    int tid = threadIdx.x, lane = tid & 31, wid = tid >> 5;
    int wm = wid & 3, wn = wid >> 2;
    uint32_t sbase = (uint32_t)__cvta_generic_to_shared(&smt[0][0]);
    uint32_t mb0   = (uint32_t)__cvta_generic_to_shared(&mbar[0]);

    if (tid == 0) {
        mbar_init(mb0, 1);
        mbar_init(mb0 + 8, 1);
        asm volatile("fence.proxy.async.shared::cta;" ::: "memory");
    }
    __syncthreads();

    const int NCH = 32;
    if (tid == 0) {
        #pragma unroll
        for (int pc = 0; pc < 2; ++pc) {
            uint32_t mb = mb0 + pc * 8;
            mbar_expect(mb, 16384);
            tma3d(sbase + pc * 16384,        mK, mbase + pc * 32, rt * 64, b,  mb);
            tma3d(sbase + pc * 16384 + 8192, mH, 0, mbase + pc * 32, zH, mb);
        }
    }

    float c[4][4];
    #pragma unroll
    for (int i = 0; i < 4; i++)
        #pragma unroll
        for (int r = 0; r < 4; r++) c[i][r] = 0.f;

    int mr = wm * 16 + (lane >> 2);
    uint32_t rx = (uint32_t)((mr & 7) << 4);   // SW128 xor term (same for mr and mr+8)

    #pragma unroll 1
    for (int cc = 0; cc < NCH; ++cc) {
        mbar_wait(mb0 + (cc & 1) * 8, (cc >> 1) & 1);
        const char*  As = &smt[cc & 1][0];
        const float* Bp = (const float*)(&smt[cc & 1][8192]);
        #pragma unroll
        for (int ks = 0; ks < 4; ++ks) {
            int kk = ks * 8 + (lane & 3);
            uint32_t co0 = ((uint32_t)(kk << 2)) ^ rx;
            uint32_t co1 = ((uint32_t)((kk + 4) << 2)) ^ rx;
            uint32_t a[4];
            a[0] = *(const uint32_t*)(As + mr * 128 + co0);
            a[1] = *(const uint32_t*)(As + (mr + 8) * 128 + co0);
            a[2] = *(const uint32_t*)(As + mr * 128 + co1);
            a[3] = *(const uint32_t*)(As + (mr + 8) * 128 + co1);
            #pragma unroll
            for (int ni = 0; ni < 4; ni++) {
                int nc = wn * 32 + ni * 8 + (lane >> 2);
                uint32_t bf[2];
                bf[0] = __float_as_uint(Bp[kk * 64 + nc]);
                bf[1] = __float_as_uint(Bp[(kk + 4) * 64 + nc]);
                mma_tf32(c[ni], a, bf);
            }
        }
        __syncthreads();
        if (tid == 0 && cc + 2 < NCH) {
            uint32_t mb = mb0 + (cc & 1) * 8;
            int m0 = mbase + (cc + 2) * 32;
            mbar_expect(mb, 16384);
            tma3d(sbase + (cc & 1) * 16384,        mK, m0, rt * 64, b,  mb);
            tma3d(sbase + (cc & 1) * 16384 + 8192, mH, 0, m0, zH, mb);
        }
    }

    #pragma unroll
    for (int ni = 0; ni < 4; ni++)
        #pragma unroll
        for (int r = 0; r < 4; r++) {
            int row = rt * 64 + wm * 16 + (lane >> 2) + ((r >> 1) << 3);
            int col = wn * 32 + ni * 8 + ((lane & 3) << 1) + (r & 1);
            Out[(size_t)row * DOUT + col] = c[ni][r];
        }
}

// ---------------- kernel: SpMM fallback (R9 cp.async version) ----------------
__global__ __launch_bounds__(256, 4) void k_spmm(int stage) {
    __shared__ float sm[2 * 4480];
    int rt = blockIdx.x, b = blockIdx.y;
    int type = blockIdx.z >> 2, sp = blockIdx.z & 3;
    int mbase = sp * (NN / 4);
    const float* Km = (type ? g_Kw : g_Kb) + (size_t)b * NN * NN;
    const float* H;
    float* Out;
    if (stage == 1) {
        H   = g_H2r + (size_t)b * NN * DOUT;
        float* outs[4] = {g_t0, g_t1, g_t2, g_t3};
        Out = outs[sp] + ((size_t)type * BB + b) * NN * DOUT;
    } else {
        H   = g_t + ((size_t)type * BB + b) * NN * DOUT;
        float* outs[4] = {g_g0, g_g1, g_g2, g_g3};
        Out = outs[sp] + ((size_t)type * BB + b) * NN * DOUT;
    }
    int tid = threadIdx.x, lane = tid & 31, wid = tid >> 5;
    int wm = wid & 3, wn = wid >> 2;
    uint32_t sb = (uint32_t)__cvta_generic_to_shared(sm);

    float c[4][4];
    #pragma unroll
    for (int i = 0; i < 4; i++)
        #pragma unroll
        for (int r = 0; r < 4; r++) c[i][r] = 0.f;

    const int NCH = 32;
    {
        uint32_t sA = sb, sB = sb + 2304 * 4;
        #pragma unroll
        for (int it = 0; it < 2; ++it) {
            int id = it * 256 + tid;
            int row = id >> 3, part = (id & 7) << 2;
            cpa16(sA + (row * 36 + part) * 4, Km + (size_t)(rt * 64 + row) * NN + mbase + part);
            int kk = id >> 4, cq = (id & 15) << 2;
            cpa16(sB + (kk * 68 + cq) * 4, H + (size_t)(mbase + kk) * DOUT + cq);
        }
    }
    CP_COMMIT();

    #pragma unroll 1
    for (int cc = 0; cc < NCH; ++cc) {
        if (cc + 1 < NCH) {
            int s = (cc + 1) & 1, m0 = mbase + (cc + 1) * 32;
            uint32_t sA = sb + (s * 4480) * 4, sB = sA + 2304 * 4;
            #pragma unroll
            for (int it = 0; it < 2; ++it) {
                int id = it * 256 + tid;
                int row = id >> 3, part = (id & 7) << 2;
                cpa16(sA + (row * 36 + part) * 4, Km + (size_t)(rt * 64 + row) * NN + m0 + part);
                int kk = id >> 4, cq = (id & 15) << 2;
                cpa16(sB + (kk * 68 + cq) * 4, H + (size_t)(m0 + kk) * DOUT + cq);
            }
        }
        CP_COMMIT();
        CP_WAIT1();
        __syncthreads();
        const float* A  = sm + (cc & 1) * 4480;
        const float* Bp = A + 2304;
        #pragma unroll
        for (int ks = 0; ks < 4; ++ks) {
            int kk = ks * 8 + (lane & 3);
            uint32_t a[4];
            int mr = wm * 16 + (lane >> 2);
            a[0] = __float_as_uint(A[mr * 36 + kk]);
            a[1] = __float_as_uint(A[(mr + 8) * 36 + kk]);
            a[2] = __float_as_uint(A[mr * 36 + kk + 4]);
            a[3] = __float_as_uint(A[(mr + 8) * 36 + kk + 4]);
            #pragma unroll
            for (int ni = 0; ni < 4; ni++) {
                int nc = wn * 32 + ni * 8 + (lane >> 2);
                uint32_t bf[2];
                bf[0] = __float_as_uint(Bp[kk * 68 + nc]);
                bf[1] = __float_as_uint(Bp[(kk + 4) * 68 + nc]);
                mma_tf32(c[ni], a, bf);
            }
        }
        __syncthreads();
    }

    #pragma unroll
    for (int ni = 0; ni < 4; ni++)
        #pragma unroll
        for (int r = 0; r < 4; r++) {
            int row = rt * 64 + wm * 16 + (lane >> 2) + ((r >> 1) << 3);
            int col = wn * 32 + ni * 8 + ((lane & 3) << 1) + (r & 1);
            Out[(size_t)row * DOUT + col] = c[ni][r];
        }
}

// ---------------- combine stage-1 partials + Add, round to tf32 --------------
__global__ void k_comb1() {
    int i = blockIdx.x * 256 + threadIdx.x;
    int col = i & 63;
    int row = (i >> 6) & (NN - 1);
    int b   = (i >> 18) & (BB - 1);
    float v = (g_t0[i] + g_t1[i]) + (g_t2[i] + g_t3[i])
            + g_P[((size_t)b * NN + row) * PC + 64 + col];
    g_t[i] = __uint_as_float(f2tf(v));
}

// ---------------- final epilogue ---------------------------------------------
__global__ void k_final(const float* __restrict__ b_lin, float* __restrict__ out) {
    int idx = blockIdx.x * 256 + threadIdx.x;
    int cidx = idx & 127;
    int n = (idx >> 7) & (NN - 1);
    int b = idx >> 19;
    int half = cidx >> 6, cc = cidx & 63;
    const float* P = g_P + ((size_t)b * NN + n) * PC;
    size_t gi = (((size_t)half * BB + b) * NN + n) * DOUT + cc;
    float g = (g_g0[gi] + g_g1[gi]) + (g_g2[gi] + g_g3[gi]);
    float v = P[cc] + g + P[192 + cidx] + b_lin[cidx];
    out[idx] = fmaxf(v, 0.f);
}

// ---------------- host-side TMA descriptor setup -----------------------------
typedef CUresult (*PFN_encodeTiled)(
    CUtensorMap*, CUtensorMapDataType, cuuint32_t, void*,
    const cuuint64_t*, const cuuint64_t*, const cuuint32_t*, const cuuint32_t*,
    CUtensorMapInterleave, CUtensorMapSwizzle, CUtensorMapL2promotion,
    CUtensorMapFloatOOBfill);

static int s_tma_state = -1;   // -1 = uninit, 0 = unavailable, 1 = ready
static CUtensorMap s_mKb, s_mKw, s_mH1, s_mH2;

static void tma_setup() {
    s_tma_state = 0;
    void* fn = nullptr;
    cudaDriverEntryPointQueryResult qr;
    if (cudaGetDriverEntryPointByVersion("cuTensorMapEncodeTiled", &fn, 12000,
                                         cudaEnableDefault, &qr) != cudaSuccess || !fn)
        return;
    PFN_encodeTiled enc = (PFN_encodeTiled)fn;

    void *pKb = nullptr, *pKw = nullptr, *pH1 = nullptr, *pH2 = nullptr;
    if (cudaGetSymbolAddress(&pKb, g_Kb)  != cudaSuccess) return;
    if (cudaGetSymbolAddress(&pKw, g_Kw)  != cudaSuccess) return;
    if (cudaGetSymbolAddress(&pH1, g_H2r) != cudaSuccess) return;
    if (cudaGetSymbolAddress(&pH2, g_t)   != cudaSuccess) return;

    cuuint32_t es[3] = {1, 1, 1};
    {   // K maps: [cols NN][rows NN][batch BB], box 32x64, SW128
        cuuint64_t dims[3]    = {NN, NN, BB};
        cuuint64_t strides[2] = {(cuuint64_t)NN * 4, (cuuint64_t)NN * NN * 4};
        cuuint32_t box[3]     = {32, 64, 1};
        if (enc(&s_mKb, CU_TENSOR_MAP_DATA_TYPE_FLOAT32, 3, pKb, dims, strides, box, es,
                CU_TENSOR_MAP_INTERLEAVE_NONE, CU_TENSOR_MAP_SWIZZLE_128B,
                CU_TENSOR_MAP_L2_PROMOTION_L2_128B, CU_TENSOR_MAP_FLOAT_OOB_FILL_NONE))
            return;
        if (enc(&s_mKw, CU_TENSOR_MAP_DATA_TYPE_FLOAT32, 3, pKw, dims, strides, box, es,
                CU_TENSOR_MAP_INTERLEAVE_NONE, CU_TENSOR_MAP_SWIZZLE_128B,
                CU_TENSOR_MAP_L2_PROMOTION_L2_128B, CU_TENSOR_MAP_FLOAT_OOB_FILL_NONE))
            return;
    }
    {   // H1: [64][NN][BB], box 64x32, no swizzle
        cuuint64_t dims[3]    = {64, NN, BB};
        cuuint64_t strides[2] = {64 * 4, (cuuint64_t)NN * 64 * 4};
        cuuint32_t box[3]     = {64, 32, 1};
        if (enc(&s_mH1, CU_TENSOR_MAP_DATA_TYPE_FLOAT32, 3, pH1, dims, strides, box, es,
                CU_TENSOR_MAP_INTERLEAVE_NONE, CU_TENSOR_MAP_SWIZZLE_NONE,
                CU_TENSOR_MAP_L2_PROMOTION_L2_128B, CU_TENSOR_MAP_FLOAT_OOB_FILL_NONE))
            return;
    }
    {   // H2: [64][NN][2*BB], box 64x32, no swizzle
        cuuint64_t dims[3]    = {64, NN, 2 * BB};
        cuuint64_t strides[2] = {64 * 4, (cuuint64_t)NN * 64 * 4};
        cuuint32_t box[3]     = {64, 32, 1};
        if (enc(&s_mH2, CU_TENSOR_MAP_DATA_TYPE_FLOAT32, 3, pH2, dims, strides, box, es,
                CU_TENSOR_MAP_INTERLEAVE_NONE, CU_TENSOR_MAP_SWIZZLE_NONE,
                CU_TENSOR_MAP_L2_PROMOTION_L2_128B, CU_TENSOR_MAP_FLOAT_OOB_FILL_NONE))
            return;
    }
    s_tma_state = 1;
}

// ---------------- launch -----------------------------------------------------
extern "C" void kernel_launch(void* const* d_in, const int* in_sizes, int n_in,
                              void* d_out, int out_size) {
    const float* x  = (const float*)d_in[0];
    const float* Wk = (const float*)d_in[1];
    const float* Wl = (const float*)d_in[2];
    const float* bl = (const float*)d_in[3];
    float* out = (float*)d_out;

    if (s_tma_state < 0) tma_setup();

    k_xcvt<<<(BB * NN * DD / 4) / 256, 256>>>(x);
    k_sqnorm<<<BB * NN / 8, 256>>>(x);
    k_wcat<<<(DD * PC + 255) / 256, 256>>>(Wk, Wl);
    k_gram<<<dim3(1056, BB), 256>>>();
    k_proj<<<dim3(PC / 64, (BB * NN) / 128), 256>>>();
    if (s_tma_state == 1) {
        k_spmm_tma<<<dim3(NN / 64, BB, 8), 256>>>(1, s_mKb, s_mKw, s_mH1, s_mH2);
        k_comb1<<<(2 * BB * NN * DOUT) / 256, 256>>>();
        k_spmm_tma<<<dim3(NN / 64, BB, 8), 256>>>(2, s_mKb, s_mKw, s_mH1, s_mH2);
    } else {
        k_spmm<<<dim3(NN / 64, BB, 8), 256>>>(1);
        k_comb1<<<(2 * BB * NN * DOUT) / 256, 256>>>();
        k_spmm<<<dim3(NN / 64, BB, 8), 256>>>(2);
    }
    k_final<<<(BB * NN * 128) / 256, 256>>>(bl, out);
}

// round 12
// speedup vs baseline: 1.4569x; 1.4569x over previous
#include <cuda_runtime.h>
#include <cuda_fp16.h>
#include <cstdint>

#define BB   2
#define NN   4096
#define DD   256
#define PC   320     // 3*64 (Wk) + 128 (W_lin)
#define DOUT 64

// ---------------- scratch ---------------------------------------------------
__device__ __half g_Kb[(size_t)BB * NN * NN];      // fp16 kernel matrices
__device__ __half g_Kw[(size_t)BB * NN * NN];
__device__ float  g_sq[BB * NN];
__device__ float  g_Wcat[DD * PC];                 // tf32-rounded
__device__ float  g_Xt[(size_t)BB * NN * DD];      // tf32-rounded x
__device__ float  g_P[(size_t)BB * NN * PC];       // fp32 x@Wcat
__device__ __half g_H2T[(size_t)BB * DOUT * NN];   // h2^T, fp16 [b][col][row]
__device__ __half g_tT[(size_t)4 * DOUT * NN];     // stage-1^T, fp16 [tb][col][row]
__device__ float  g_t0[(size_t)2 * BB * NN * DOUT];
__device__ float  g_t1[(size_t)2 * BB * NN * DOUT];
__device__ float  g_t2[(size_t)2 * BB * NN * DOUT];
__device__ float  g_t3[(size_t)2 * BB * NN * DOUT];
__device__ float  g_g0[(size_t)2 * BB * NN * DOUT];
__device__ float  g_g1[(size_t)2 * BB * NN * DOUT];
__device__ float  g_g2[(size_t)2 * BB * NN * DOUT];
__device__ float  g_g3[(size_t)2 * BB * NN * DOUT];

// ---------------- helpers ---------------------------------------------------
__device__ __forceinline__ uint32_t f2tf(float f) {
    uint32_t u;
    asm volatile("cvt.rna.tf32.f32 %0, %1;" : "=r"(u) : "f"(f));
    return u;
}

__device__ __forceinline__ void mma_tf32(float c[4], const uint32_t a[4], const uint32_t b[2]) {
    asm volatile(
        "mma.sync.aligned.m16n8k8.row.col.f32.tf32.tf32.f32 "
        "{%0,%1,%2,%3}, {%4,%5,%6,%7}, {%8,%9}, {%0,%1,%2,%3};\n"
        : "+f"(c[0]), "+f"(c[1]), "+f"(c[2]), "+f"(c[3])
        : "r"(a[0]), "r"(a[1]), "r"(a[2]), "r"(a[3]),
          "r"(b[0]), "r"(b[1]));
}

__device__ __forceinline__ void mma_f16(float c[4], const uint32_t a[4], const uint32_t b[2]) {
    asm volatile(
        "mma.sync.aligned.m16n8k16.row.col.f32.f16.f16.f32 "
        "{%0,%1,%2,%3}, {%4,%5,%6,%7}, {%8,%9}, {%0,%1,%2,%3};\n"
        : "+f"(c[0]), "+f"(c[1]), "+f"(c[2]), "+f"(c[3])
        : "r"(a[0]), "r"(a[1]), "r"(a[2]), "r"(a[3]),
          "r"(b[0]), "r"(b[1]));
}

__device__ __forceinline__ void cpa16(uint32_t dst, const void* src) {
    asm volatile("cp.async.cg.shared.global [%0], [%1], 16;\n" :: "r"(dst), "l"(src));
}
#define CP_COMMIT() asm volatile("cp.async.commit_group;\n" ::: "memory")
#define CP_WAIT1()  asm volatile("cp.async.wait_group 1;\n" ::: "memory")

// Closed-form cubic B-spline on uniform knots {0,.25,.5,.75,1} (== reference).
__device__ __forceinline__ float b3fold(float v) {
    float outer = v * v * v * (1.f / 6.f);
    float inner = (((-3.f * v + 12.f) * v - 12.f) * v + 4.f) * (1.f / 6.f);
    return (v < 1.f) ? outer : inner;
}
__device__ __forceinline__ float bk_eval(float t) {
    float v = 2.f - fabsf(4.f * t - 2.f);
    return b3fold(v);
}
__device__ __forceinline__ float wk_eval(float t) {
    float sg = 8.f * t;
    bool lo = (sg < 4.f);
    float sp = lo ? sg : sg - 4.f;
    float v = 2.f - fabsf(sp - 2.f);
    float r = b3fold(v);
    return lo ? r : -r;
}

// ---------------- tiny prep kernels -----------------------------------------
__global__ void k_xcvt(const float* __restrict__ x) {
    int i = blockIdx.x * 256 + threadIdx.x;
    float4 v = ((const float4*)x)[i];
    uint4 o;
    o.x = f2tf(v.x); o.y = f2tf(v.y); o.z = f2tf(v.z); o.w = f2tf(v.w);
    ((uint4*)g_Xt)[i] = o;
}

__global__ void k_sqnorm(const float* __restrict__ x) {
    int row  = blockIdx.x * 8 + (threadIdx.x >> 5);
    int lane = threadIdx.x & 31;
    const float* xr = x + (size_t)row * DD;
    float s = 0.f;
    #pragma unroll
    for (int i = lane; i < DD; i += 32) { float v = xr[i]; s += v * v; }
    #pragma unroll
    for (int o = 16; o; o >>= 1) s += __shfl_xor_sync(0xffffffffu, s, o);
    if (lane == 0) g_sq[row] = s;
}

__global__ void k_wcat(const float* __restrict__ Wk, const float* __restrict__ Wl) {
    int i = blockIdx.x * 256 + threadIdx.x;
    if (i >= DD * PC) return;
    int d = i / PC, cidx = i % PC;
    float v;
    if (cidx < 192) v = Wk[(size_t)(cidx / 64) * DD * 64 + (size_t)d * 64 + (cidx & 63)];
    else            v = Wl[(size_t)d * 128 + (cidx - 192)];
    g_Wcat[i] = __uint_as_float(f2tf(v));
}

// ---------------- kernel: Gram + spline (R9 loop, fp16 stores) ---------------
__global__ __launch_bounds__(256, 4) void k_gram() {
    __shared__ float sm[2 * 3840];
    int h   = blockIdx.x & 1;
    int idx = blockIdx.x >> 1;
    int b   = blockIdx.y;
    int tj = (int)((sqrtf(8.f * idx + 1.f) - 1.f) * 0.5f);
    while ((tj + 1) * (tj + 2) / 2 <= idx) ++tj;
    while (tj * (tj + 1) / 2 > idx) --tj;
    int ti = idx - tj * (tj + 1) / 2;

    int tid = threadIdx.x, lane = tid & 31, wid = tid >> 5;
    int wm = wid & 3, wn = wid >> 2;
    const float* Xa = g_Xt + ((size_t)b * NN + (size_t)ti * 128) * DD;
    const float* Xb = g_Xt + ((size_t)b * NN + (size_t)tj * 128 + (size_t)h * 64) * DD;
    uint32_t sb = (uint32_t)__cvta_generic_to_shared(sm);

    float c[2][4][4];
    #pragma unroll
    for (int i = 0; i < 2; i++)
        #pragma unroll
        for (int j = 0; j < 4; j++)
            #pragma unroll
            for (int r = 0; r < 4; r++) c[i][j][r] = 0.f;

    int arow_l = tid >> 2,         apart_l = (tid & 3) << 2;
    int arow_h = (256 + tid) >> 2, apart_h = ((256 + tid) & 3) << 2;
    int brow   = tid >> 2,         bpart   = (tid & 3) << 2;

    {
        uint32_t sA = sb, sB = sb + 2560 * 4;
        cpa16(sA + (arow_l * 20 + apart_l) * 4, Xa + (size_t)arow_l * DD + apart_l);
        cpa16(sA + (arow_h * 20 + apart_h) * 4, Xa + (size_t)arow_h * DD + apart_h);
        cpa16(sB + (brow * 20 + bpart) * 4, Xb + (size_t)brow * DD + bpart);
    }
    CP_COMMIT();

    for (int cc = 0; cc < 16; ++cc) {
        if (cc + 1 < 16) {
            int s = (cc + 1) & 1, k0 = (cc + 1) * 16;
            uint32_t sA = sb + (s * 3840) * 4, sB = sA + 2560 * 4;
            cpa16(sA + (arow_l * 20 + apart_l) * 4, Xa + (size_t)arow_l * DD + k0 + apart_l);
            cpa16(sA + (arow_h * 20 + apart_h) * 4, Xa + (size_t)arow_h * DD + k0 + apart_h);
            cpa16(sB + (brow * 20 + bpart) * 4, Xb + (size_t)brow * DD + k0 + bpart);
        }
        CP_COMMIT();
        CP_WAIT1();
        __syncthreads();
        const float* A  = sm + (cc & 1) * 3840;
        const float* Bp = A + 2560;
        #pragma unroll
        for (int ks = 0; ks < 2; ++ks) {
            int kk = ks * 8 + (lane & 3);
            uint32_t a[2][4], bf[4][2];
            #pragma unroll
            for (int mi = 0; mi < 2; mi++) {
                int mr = wm * 32 + mi * 16 + (lane >> 2);
                a[mi][0] = __float_as_uint(A[mr * 20 + kk]);
                a[mi][1] = __float_as_uint(A[(mr + 8) * 20 + kk]);
                a[mi][2] = __float_as_uint(A[mr * 20 + kk + 4]);
                a[mi][3] = __float_as_uint(A[(mr + 8) * 20 + kk + 4]);
            }
            #pragma unroll
            for (int ni = 0; ni < 4; ni++) {
                int nc = wn * 32 + ni * 8 + (lane >> 2);
                bf[ni][0] = __float_as_uint(Bp[nc * 20 + kk]);
                bf[ni][1] = __float_as_uint(Bp[nc * 20 + kk + 4]);
            }
            #pragma unroll
            for (int mi = 0; mi < 2; mi++)
                #pragma unroll
                for (int ni = 0; ni < 4; ni++)
                    mma_tf32(c[mi][ni], a[mi], bf[ni]);
        }
        __syncthreads();
    }

    __half* Kb = g_Kb + (size_t)b * NN * NN;
    __half* Kw = g_Kw + (size_t)b * NN * NN;
    const float* sq = g_sq + b * NN;
    int i0 = ti * 128 + wm * 32, j0 = tj * 128 + h * 64 + wn * 32;
    bool mir = (ti != tj);
    #pragma unroll
    for (int mi = 0; mi < 2; mi++)
        #pragma unroll
        for (int ni = 0; ni < 4; ni++)
            #pragma unroll
            for (int r = 0; r < 4; r++) {
                int i = i0 + mi * 16 + (lane >> 2) + ((r >> 1) << 3);
                int j = j0 + ni * 8 + ((lane & 3) << 1) + (r & 1);
                float d2 = sq[i] + sq[j] - 2.f * c[mi][ni][r];
                d2 = fmaxf(d2, 0.f);
                float t = __expf(d2 * (-1.f / 512.f));
                __half bk = __float2half_rn(bk_eval(t));
                __half wk = __float2half_rn(wk_eval(t));
                Kb[(size_t)i * NN + j] = bk;
                Kw[(size_t)i * NN + j] = wk;
                if (mir) {
                    Kb[(size_t)j * NN + i] = bk;
                    Kw[(size_t)j * NN + i] = wk;
                }
            }
}

// ---------------- kernel: projection P = x @ Wcat ----------------------------
__global__ __launch_bounds__(256) void k_proj() {
    __shared__ float sm[2 * 3648];
    int c0 = blockIdx.x * 64, byr = blockIdx.y;
    int tid = threadIdx.x, lane = tid & 31, wid = tid >> 5;
    int wm = wid & 1, wn = wid >> 1;
    const float* Xa = g_Xt + (size_t)byr * 128 * DD;
    uint32_t sb = (uint32_t)__cvta_generic_to_shared(sm);

    float c[4][2][4];
    #pragma unroll
    for (int i = 0; i < 4; i++)
        #pragma unroll
        for (int j = 0; j < 2; j++)
            #pragma unroll
            for (int r = 0; r < 4; r++) c[i][j][r] = 0.f;

    {
        uint32_t sA = sb, sB = sb + 2560 * 4;
        #pragma unroll
        for (int it = 0; it < 2; ++it) {
            int id = it * 256 + tid;
            int row = id >> 2, part = (id & 3) << 2;
            cpa16(sA + (row * 20 + part) * 4, Xa + (size_t)row * DD + part);
        }
        int kk = tid >> 4, cq = (tid & 15) << 2;
        cpa16(sB + (kk * 68 + cq) * 4, g_Wcat + (size_t)kk * PC + c0 + cq);
    }
    CP_COMMIT();

    for (int cc = 0; cc < 16; ++cc) {
        if (cc + 1 < 16) {
            int s = (cc + 1) & 1, k0 = (cc + 1) * 16;
            uint32_t sA = sb + (s * 3648) * 4, sB = sA + 2560 * 4;
            #pragma unroll
            for (int it = 0; it < 2; ++it) {
                int id = it * 256 + tid;
                int row = id >> 2, part = (id & 3) << 2;
                cpa16(sA + (row * 20 + part) * 4, Xa + (size_t)row * DD + k0 + part);
            }
            int kk = tid >> 4, cq = (tid & 15) << 2;
            cpa16(sB + (kk * 68 + cq) * 4, g_Wcat + (size_t)(k0 + kk) * PC + c0 + cq);
        }
        CP_COMMIT();
        CP_WAIT1();
        __syncthreads();
        const float* A  = sm + (cc & 1) * 3648;
        const float* Bp = A + 2560;
        #pragma unroll
        for (int ks = 0; ks < 2; ++ks) {
            int kk = ks * 8 + (lane & 3);
            uint32_t a[4][4], bf[2][2];
            #pragma unroll
            for (int mi = 0; mi < 4; mi++) {
                int mr = wm * 64 + mi * 16 + (lane >> 2);
                a[mi][0] = __float_as_uint(A[mr * 20 + kk]);
                a[mi][1] = __float_as_uint(A[(mr + 8) * 20 + kk]);
                a[mi][2] = __float_as_uint(A[mr * 20 + kk + 4]);
                a[mi][3] = __float_as_uint(A[(mr + 8) * 20 + kk + 4]);
            }
            #pragma unroll
            for (int ni = 0; ni < 2; ni++) {
                int nc = wn * 16 + ni * 8 + (lane >> 2);
                bf[ni][0] = __float_as_uint(Bp[kk * 68 + nc]);
                bf[ni][1] = __float_as_uint(Bp[(kk + 4) * 68 + nc]);
            }
            #pragma unroll
            for (int mi = 0; mi < 4; mi++)
                #pragma unroll
                for (int ni = 0; ni < 2; ni++)
                    mma_tf32(c[mi][ni], a[mi], bf[ni]);
        }
        __syncthreads();
    }

    #pragma unroll
    for (int mi = 0; mi < 4; mi++)
        #pragma unroll
        for (int ni = 0; ni < 2; ni++)
            #pragma unroll
            for (int r = 0; r < 4; r++) {
                int row = byr * 128 + wm * 64 + mi * 16 + (lane >> 2) + ((r >> 1) << 3);
                int col = c0 + wn * 16 + ni * 8 + ((lane & 3) << 1) + (r & 1);
                g_P[(size_t)row * PC + col] = c[mi][ni][r];
            }
}

// ---------------- kernel: H2^T fp16 from g_P (smem transpose) ----------------
__global__ __launch_bounds__(256) void k_h2t() {
    __shared__ __half sh[64][72];
    int r0 = blockIdx.x * 64;
    int t = threadIdx.x;
    int r = t >> 2, cq = (t & 3) * 16;
    const float* src = g_P + (size_t)(r0 + r) * PC + 128 + cq;
    #pragma unroll
    for (int q = 0; q < 4; ++q) {
        float4 v = *(const float4*)(src + q * 4);
        sh[r][cq + q * 4 + 0] = __float2half_rn(v.x);
        sh[r][cq + q * 4 + 1] = __float2half_rn(v.y);
        sh[r][cq + q * 4 + 2] = __float2half_rn(v.z);
        sh[r][cq + q * 4 + 3] = __float2half_rn(v.w);
    }
    __syncthreads();
    int c = t >> 2, rq = (t & 3) * 16;
    int b = r0 >> 12, n0 = r0 & (NN - 1);
    __half* dst = g_H2T + ((size_t)b * DOUT + c) * NN + n0 + rq;
    #pragma unroll
    for (int q = 0; q < 16; ++q) dst[q] = sh[rq + q][c];
}

// ---------------- kernel: SpMM fp16, split-K x4, 2-stage cp.async ------------
__global__ __launch_bounds__(256, 4) void k_spmm16(int stage) {
    __shared__ uint32_t sm[2 * 2560];     // per stage: A 64*20 + B 64*20 u32
    int rt = blockIdx.x, b = blockIdx.y;
    int type = blockIdx.z >> 2, sp = blockIdx.z & 3;
    int mbase = sp * (NN / 4);
    const __half* Km = (type ? g_Kw : g_Kb) + (size_t)b * NN * NN;
    const __half* Ht;
    float* Out;
    if (stage == 1) {
        Ht = g_H2T + (size_t)b * DOUT * NN;
        float* o4[4] = {g_t0, g_t1, g_t2, g_t3};
        Out = o4[sp] + ((size_t)type * BB + b) * NN * DOUT;
    } else {
        Ht = g_tT + (size_t)(type * BB + b) * DOUT * NN;
        float* o4[4] = {g_g0, g_g1, g_g2, g_g3};
        Out = o4[sp] + ((size_t)type * BB + b) * NN * DOUT;
    }
    int tid = threadIdx.x, lane = tid & 31, wid = tid >> 5;
    int wm = wid & 3, wn = wid >> 2;
    uint32_t sb = (uint32_t)__cvta_generic_to_shared(sm);

    float c[4][4];
    #pragma unroll
    for (int i = 0; i < 4; i++)
        #pragma unroll
        for (int r = 0; r < 4; r++) c[i][r] = 0.f;

    int arow = tid >> 2, apart = tid & 3;
    const int NCH = 32;
    {
        uint32_t sA = sb, sB = sb + 1280 * 4;
        cpa16(sA + (arow * 20 + apart * 4) * 4, Km + (size_t)(rt * 64 + arow) * NN + mbase + apart * 8);
        cpa16(sB + (arow * 20 + apart * 4) * 4, Ht + (size_t)arow * NN + mbase + apart * 8);
    }
    CP_COMMIT();

    #pragma unroll 1
    for (int cc = 0; cc < NCH; ++cc) {
        if (cc + 1 < NCH) {
            int s = (cc + 1) & 1, m0 = mbase + (cc + 1) * 32;
            uint32_t sA = sb + (s * 2560) * 4, sB = sA + 1280 * 4;
            cpa16(sA + (arow * 20 + apart * 4) * 4, Km + (size_t)(rt * 64 + arow) * NN + m0 + apart * 8);
            cpa16(sB + (arow * 20 + apart * 4) * 4, Ht + (size_t)arow * NN + m0 + apart * 8);
        }
        CP_COMMIT();
        CP_WAIT1();
        __syncthreads();
        const uint32_t* A  = sm + (cc & 1) * 2560;
        const uint32_t* Bp = A + 1280;
        int mr = wm * 16 + (lane >> 2);
        #pragma unroll
        for (int ks = 0; ks < 2; ++ks) {
            int kb = ks * 8 + (lane & 3);
            uint32_t a[4];
            a[0] = A[mr * 20 + kb];
            a[1] = A[(mr + 8) * 20 + kb];
            a[2] = A[mr * 20 + kb + 4];
            a[3] = A[(mr + 8) * 20 + kb + 4];
            #pragma unroll
            for (int ni = 0; ni < 4; ni++) {
                int nc = wn * 32 + ni * 8 + (lane >> 2);
                uint32_t bf[2];
                bf[0] = Bp[nc * 20 + kb];
                bf[1] = Bp[nc * 20 + kb + 4];
                mma_f16(c[ni], a, bf);
            }
        }
        __syncthreads();
    }

    #pragma unroll
    for (int ni = 0; ni < 4; ni++)
        #pragma unroll
        for (int r = 0; r < 4; r++) {
            int row = rt * 64 + wm * 16 + (lane >> 2) + ((r >> 1) << 3);
            int col = wn * 32 + ni * 8 + ((lane & 3) << 1) + (r & 1);
            Out[(size_t)row * DOUT + col] = c[ni][r];
        }
}

// ---------------- combine stage-1 partials + h1, write fp16 transposed -------
__global__ __launch_bounds__(256) void k_comb1t() {
    __shared__ __half sh[64][72];
    int n0 = blockIdx.x * 64, tb = blockIdx.y;
    int b = tb & 1;
    int t = threadIdx.x;
    int r = t >> 2, cq = (t & 3) * 16;
    size_t base = ((size_t)tb * NN + n0 + r) * DOUT + cq;
    const float* P = g_P + ((size_t)b * NN + n0 + r) * PC + 64 + cq;
    #pragma unroll
    for (int q = 0; q < 4; ++q) {
        float4 v0 = *(const float4*)(g_t0 + base + q * 4);
        float4 v1 = *(const float4*)(g_t1 + base + q * 4);
        float4 v2 = *(const float4*)(g_t2 + base + q * 4);
        float4 v3 = *(const float4*)(g_t3 + base + q * 4);
        float4 vp = *(const float4*)(P + q * 4);
        sh[r][cq + q * 4 + 0] = __float2half_rn((v0.x + v1.x) + (v2.x + v3.x) + vp.x);
        sh[r][cq + q * 4 + 1] = __float2half_rn((v0.y + v1.y) + (v2.y + v3.y) + vp.y);
        sh[r][cq + q * 4 + 2] = __float2half_rn((v0.z + v1.z) + (v2.z + v3.z) + vp.z);
        sh[r][cq + q * 4 + 3] = __float2half_rn((v0.w + v1.w) + (v2.w + v3.w) + vp.w);
    }
    __syncthreads();
    int c = t >> 2, rq = (t & 3) * 16;
    __half* dst = g_tT + ((size_t)tb * DOUT + c) * NN + n0 + rq;
    #pragma unroll
    for (int q = 0; q < 16; ++q) dst[q] = sh[rq + q][c];
}

// ---------------- final epilogue ---------------------------------------------
__global__ void k_final(const float* __restrict__ b_lin, float* __restrict__ out) {
    int idx = blockIdx.x * 256 + threadIdx.x;
    int cidx = idx & 127;
    int n = (idx >> 7) & (NN - 1);
    int b = idx >> 19;
    int half = cidx >> 6, cc = cidx & 63;
    const float* P = g_P + ((size_t)b * NN + n) * PC;
    size_t gi = (((size_t)half * BB + b) * NN + n) * DOUT + cc;
    float g = (g_g0[gi] + g_g1[gi]) + (g_g2[gi] + g_g3[gi]);
    float v = P[cc] + g + P[192 + cidx] + b_lin[cidx];
    out[idx] = fmaxf(v, 0.f);
}

// ---------------- launch -----------------------------------------------------
extern "C" void kernel_launch(void* const* d_in, const int* in_sizes, int n_in,
                              void* d_out, int out_size) {
    const float* x  = (const float*)d_in[0];
    const float* Wk = (const float*)d_in[1];
    const float* Wl = (const float*)d_in[2];
    const float* bl = (const float*)d_in[3];
    float* out = (float*)d_out;

    k_xcvt<<<(BB * NN * DD / 4) / 256, 256>>>(x);
    k_sqnorm<<<BB * NN / 8, 256>>>(x);
    k_wcat<<<(DD * PC + 255) / 256, 256>>>(Wk, Wl);
    k_gram<<<dim3(1056, BB), 256>>>();
    k_proj<<<dim3(PC / 64, (BB * NN) / 128), 256>>>();
    k_h2t<<<(BB * NN) / 64, 256>>>();
    k_spmm16<<<dim3(NN / 64, BB, 8), 256>>>(1);
    k_comb1t<<<dim3(NN / 64, 4), 256>>>();
    k_spmm16<<<dim3(NN / 64, BB, 8), 256>>>(2);
    k_final<<<(BB * NN * 128) / 256, 256>>>(bl, out);
}

// round 13
// speedup vs baseline: 1.6028x; 1.1001x over previous
#include <cuda_runtime.h>
#include <cuda_fp16.h>
#include <cstdint>

#define BB   2
#define NN   4096
#define DD   256
#define PC   320     // 3*64 (Wk) + 128 (W_lin)
#define DOUT 64

// ---------------- scratch ---------------------------------------------------
__device__ __half g_Kb[(size_t)BB * NN * NN];      // fp16 kernel matrices
__device__ __half g_Kw[(size_t)BB * NN * NN];
__device__ float  g_sq[BB * NN];
__device__ float  g_Wcat[DD * PC];                 // tf32-rounded
__device__ float  g_Xt[(size_t)BB * NN * DD];      // tf32-rounded x (for proj)
__device__ __half g_Xh[(size_t)BB * NN * DD];      // fp16 x (for gram)
__device__ float  g_P[(size_t)BB * NN * PC];       // fp32 x@Wcat
__device__ __half g_H2T[(size_t)BB * DOUT * NN];   // h2^T, fp16 [b][col][row]
__device__ __half g_tT[(size_t)4 * DOUT * NN];     // stage-1^T, fp16 [tb][col][row]
__device__ float  g_t0[(size_t)2 * BB * NN * DOUT];
__device__ float  g_t1[(size_t)2 * BB * NN * DOUT];
__device__ float  g_t2[(size_t)2 * BB * NN * DOUT];
__device__ float  g_t3[(size_t)2 * BB * NN * DOUT];
__device__ float  g_g0[(size_t)2 * BB * NN * DOUT];
__device__ float  g_g1[(size_t)2 * BB * NN * DOUT];
__device__ float  g_g2[(size_t)2 * BB * NN * DOUT];
__device__ float  g_g3[(size_t)2 * BB * NN * DOUT];

// ---------------- helpers ---------------------------------------------------
__device__ __forceinline__ uint32_t f2tf(float f) {
    uint32_t u;
    asm volatile("cvt.rna.tf32.f32 %0, %1;" : "=r"(u) : "f"(f));
    return u;
}

__device__ __forceinline__ void mma_tf32(float c[4], const uint32_t a[4], const uint32_t b[2]) {
    asm volatile(
        "mma.sync.aligned.m16n8k8.row.col.f32.tf32.tf32.f32 "
        "{%0,%1,%2,%3}, {%4,%5,%6,%7}, {%8,%9}, {%0,%1,%2,%3};\n"
        : "+f"(c[0]), "+f"(c[1]), "+f"(c[2]), "+f"(c[3])
        : "r"(a[0]), "r"(a[1]), "r"(a[2]), "r"(a[3]),
          "r"(b[0]), "r"(b[1]));
}

__device__ __forceinline__ void mma_f16(float c[4], const uint32_t a[4], const uint32_t b[2]) {
    asm volatile(
        "mma.sync.aligned.m16n8k16.row.col.f32.f16.f16.f32 "
        "{%0,%1,%2,%3}, {%4,%5,%6,%7}, {%8,%9}, {%0,%1,%2,%3};\n"
        : "+f"(c[0]), "+f"(c[1]), "+f"(c[2]), "+f"(c[3])
        : "r"(a[0]), "r"(a[1]), "r"(a[2]), "r"(a[3]),
          "r"(b[0]), "r"(b[1]));
}

__device__ __forceinline__ void cpa16(uint32_t dst, const void* src) {
    asm volatile("cp.async.cg.shared.global [%0], [%1], 16;\n" :: "r"(dst), "l"(src));
}
#define CP_COMMIT() asm volatile("cp.async.commit_group;\n" ::: "memory")
#define CP_WAIT1()  asm volatile("cp.async.wait_group 1;\n" ::: "memory")

// Closed-form cubic B-spline on uniform knots {0,.25,.5,.75,1} (== reference).
__device__ __forceinline__ float b3fold(float v) {
    float outer = v * v * v * (1.f / 6.f);
    float inner = (((-3.f * v + 12.f) * v - 12.f) * v + 4.f) * (1.f / 6.f);
    return (v < 1.f) ? outer : inner;
}
__device__ __forceinline__ float bk_eval(float t) {
    float v = 2.f - fabsf(4.f * t - 2.f);
    return b3fold(v);
}
__device__ __forceinline__ float wk_eval(float t) {
    float sg = 8.f * t;
    bool lo = (sg < 4.f);
    float sp = lo ? sg : sg - 4.f;
    float v = 2.f - fabsf(sp - 2.f);
    float r = b3fold(v);
    return lo ? r : -r;
}

// ---------------- tiny prep kernels -----------------------------------------
__global__ void k_xcvt(const float* __restrict__ x) {
    int i = blockIdx.x * 256 + threadIdx.x;
    float4 v = ((const float4*)x)[i];
    uint4 o;
    o.x = f2tf(v.x); o.y = f2tf(v.y); o.z = f2tf(v.z); o.w = f2tf(v.w);
    ((uint4*)g_Xt)[i] = o;
    __half2 h0 = __floats2half2_rn(v.x, v.y);
    __half2 h1 = __floats2half2_rn(v.z, v.w);
    uint2 ho;
    ho.x = *(uint32_t*)&h0;
    ho.y = *(uint32_t*)&h1;
    ((uint2*)g_Xh)[i] = ho;
}

__global__ void k_sqnorm(const float* __restrict__ x) {
    int row  = blockIdx.x * 8 + (threadIdx.x >> 5);
    int lane = threadIdx.x & 31;
    const float* xr = x + (size_t)row * DD;
    float s = 0.f;
    #pragma unroll
    for (int i = lane; i < DD; i += 32) { float v = xr[i]; s += v * v; }
    #pragma unroll
    for (int o = 16; o; o >>= 1) s += __shfl_xor_sync(0xffffffffu, s, o);
    if (lane == 0) g_sq[row] = s;
}

__global__ void k_wcat(const float* __restrict__ Wk, const float* __restrict__ Wl) {
    int i = blockIdx.x * 256 + threadIdx.x;
    if (i >= DD * PC) return;
    int d = i / PC, cidx = i % PC;
    float v;
    if (cidx < 192) v = Wk[(size_t)(cidx / 64) * DD * 64 + (size_t)d * 64 + (cidx & 63)];
    else            v = Wl[(size_t)d * 128 + (cidx - 192)];
    g_Wcat[i] = __uint_as_float(f2tf(v));
}

// ---------------- kernel: Gram + spline (fp16 mainloop) ----------------------
// Block tile 128(m) x 64(n); 8 warps 4m x 2n, warp tile 32x32.
// KC=32 halves/chunk (64B/row), 8 chunks. Rows padded to 20 u32 (80B).
// smem: 2 stages x (A 128x20 + B 64x20) u32 = 30 KB. 4 blocks/SM.
__global__ __launch_bounds__(256, 4) void k_gram() {
    __shared__ uint32_t sm[2 * 3840];
    int h   = blockIdx.x & 1;
    int idx = blockIdx.x >> 1;
    int b   = blockIdx.y;
    int tj = (int)((sqrtf(8.f * idx + 1.f) - 1.f) * 0.5f);
    while ((tj + 1) * (tj + 2) / 2 <= idx) ++tj;
    while (tj * (tj + 1) / 2 > idx) --tj;
    int ti = idx - tj * (tj + 1) / 2;

    int tid = threadIdx.x, lane = tid & 31, wid = tid >> 5;
    int wm = wid & 3, wn = wid >> 2;
    const __half* Xa = g_Xh + ((size_t)b * NN + (size_t)ti * 128) * DD;
    const __half* Xb = g_Xh + ((size_t)b * NN + (size_t)tj * 128 + (size_t)h * 64) * DD;
    uint32_t sb = (uint32_t)__cvta_generic_to_shared(sm);

    float c[2][4][4];
    #pragma unroll
    for (int i = 0; i < 2; i++)
        #pragma unroll
        for (int j = 0; j < 4; j++)
            #pragma unroll
            for (int r = 0; r < 4; r++) c[i][j][r] = 0.f;

    // A: 128 rows x 4 parts (16B each) = 512 -> 2/thread. B: 64 x 4 = 256 -> 1/thread.
    int arow_l = tid >> 2,         apart_l = tid & 3;
    int arow_h = (256 + tid) >> 2, apart_h = (256 + tid) & 3;
    int brow   = tid >> 2,         bpart   = tid & 3;

    {   // prologue: chunk 0 -> stage 0
        uint32_t sA = sb, sB = sb + 2560 * 4;
        cpa16(sA + (arow_l * 20 + apart_l * 4) * 4, Xa + (size_t)arow_l * DD + apart_l * 8);
        cpa16(sA + (arow_h * 20 + apart_h * 4) * 4, Xa + (size_t)arow_h * DD + apart_h * 8);
        cpa16(sB + (brow * 20 + bpart * 4) * 4, Xb + (size_t)brow * DD + bpart * 8);
    }
    CP_COMMIT();

    for (int cc = 0; cc < 8; ++cc) {
        if (cc + 1 < 8) {
            int s = (cc + 1) & 1, k0 = (cc + 1) * 32;
            uint32_t sA = sb + (s * 3840) * 4, sB = sA + 2560 * 4;
            cpa16(sA + (arow_l * 20 + apart_l * 4) * 4, Xa + (size_t)arow_l * DD + k0 + apart_l * 8);
            cpa16(sA + (arow_h * 20 + apart_h * 4) * 4, Xa + (size_t)arow_h * DD + k0 + apart_h * 8);
            cpa16(sB + (brow * 20 + bpart * 4) * 4, Xb + (size_t)brow * DD + k0 + bpart * 8);
        }
        CP_COMMIT();
        CP_WAIT1();
        __syncthreads();
        const uint32_t* A  = sm + (cc & 1) * 3840;
        const uint32_t* Bp = A + 2560;
        #pragma unroll
        for (int ks = 0; ks < 2; ++ks) {
            int kb = ks * 8 + (lane & 3);
            uint32_t a[2][4], bf[4][2];
            #pragma unroll
            for (int mi = 0; mi < 2; mi++) {
                int mr = wm * 32 + mi * 16 + (lane >> 2);
                a[mi][0] = A[mr * 20 + kb];
                a[mi][1] = A[(mr + 8) * 20 + kb];
                a[mi][2] = A[mr * 20 + kb + 4];
                a[mi][3] = A[(mr + 8) * 20 + kb + 4];
            }
            #pragma unroll
            for (int ni = 0; ni < 4; ni++) {
                int nc = wn * 32 + ni * 8 + (lane >> 2);
                bf[ni][0] = Bp[nc * 20 + kb];
                bf[ni][1] = Bp[nc * 20 + kb + 4];
            }
            #pragma unroll
            for (int mi = 0; mi < 2; mi++)
                #pragma unroll
                for (int ni = 0; ni < 4; ni++)
                    mma_f16(c[mi][ni], a[mi], bf[ni]);
        }
        __syncthreads();
    }

    __half* Kb = g_Kb + (size_t)b * NN * NN;
    __half* Kw = g_Kw + (size_t)b * NN * NN;
    const float* sq = g_sq + b * NN;
    int i0 = ti * 128 + wm * 32, j0 = tj * 128 + h * 64 + wn * 32;
    bool mir = (ti != tj);
    #pragma unroll
    for (int mi = 0; mi < 2; mi++)
        #pragma unroll
        for (int ni = 0; ni < 4; ni++)
            #pragma unroll
            for (int r = 0; r < 4; r++) {
                int i = i0 + mi * 16 + (lane >> 2) + ((r >> 1) << 3);
                int j = j0 + ni * 8 + ((lane & 3) << 1) + (r & 1);
                float d2 = sq[i] + sq[j] - 2.f * c[mi][ni][r];
                d2 = fmaxf(d2, 0.f);
                float t = __expf(d2 * (-1.f / 512.f));
                __half bk = __float2half_rn(bk_eval(t));
                __half wk = __float2half_rn(wk_eval(t));
                Kb[(size_t)i * NN + j] = bk;
                Kw[(size_t)i * NN + j] = wk;
                if (mir) {
                    Kb[(size_t)j * NN + i] = bk;
                    Kw[(size_t)j * NN + i] = wk;
                }
            }
}

// ---------------- kernel: projection P = x @ Wcat (tf32, unchanged) ----------
__global__ __launch_bounds__(256) void k_proj() {
    __shared__ float sm[2 * 3648];
    int c0 = blockIdx.x * 64, byr = blockIdx.y;
    int tid = threadIdx.x, lane = tid & 31, wid = tid >> 5;
    int wm = wid & 1, wn = wid >> 1;
    const float* Xa = g_Xt + (size_t)byr * 128 * DD;
    uint32_t sb = (uint32_t)__cvta_generic_to_shared(sm);

    float c[4][2][4];
    #pragma unroll
    for (int i = 0; i < 4; i++)
        #pragma unroll
        for (int j = 0; j < 2; j++)
            #pragma unroll
            for (int r = 0; r < 4; r++) c[i][j][r] = 0.f;

    {
        uint32_t sA = sb, sB = sb + 2560 * 4;
        #pragma unroll
        for (int it = 0; it < 2; ++it) {
            int id = it * 256 + tid;
            int row = id >> 2, part = (id & 3) << 2;
            cpa16(sA + (row * 20 + part) * 4, Xa + (size_t)row * DD + part);
        }
        int kk = tid >> 4, cq = (tid & 15) << 2;
        cpa16(sB + (kk * 68 + cq) * 4, g_Wcat + (size_t)kk * PC + c0 + cq);
    }
    CP_COMMIT();

    for (int cc = 0; cc < 16; ++cc) {
        if (cc + 1 < 16) {
            int s = (cc + 1) & 1, k0 = (cc + 1) * 16;
            uint32_t sA = sb + (s * 3648) * 4, sB = sA + 2560 * 4;
            #pragma unroll
            for (int it = 0; it < 2; ++it) {
                int id = it * 256 + tid;
                int row = id >> 2, part = (id & 3) << 2;
                cpa16(sA + (row * 20 + part) * 4, Xa + (size_t)row * DD + k0 + part);
            }
            int kk = tid >> 4, cq = (tid & 15) << 2;
            cpa16(sB + (kk * 68 + cq) * 4, g_Wcat + (size_t)(k0 + kk) * PC + c0 + cq);
        }
        CP_COMMIT();
        CP_WAIT1();
        __syncthreads();
        const float* A  = sm + (cc & 1) * 3648;
        const float* Bp = A + 2560;
        #pragma unroll
        for (int ks = 0; ks < 2; ++ks) {
            int kk = ks * 8 + (lane & 3);
            uint32_t a[4][4], bf[2][2];
            #pragma unroll
            for (int mi = 0; mi < 4; mi++) {
                int mr = wm * 64 + mi * 16 + (lane >> 2);
                a[mi][0] = __float_as_uint(A[mr * 20 + kk]);
                a[mi][1] = __float_as_uint(A[(mr + 8) * 20 + kk]);
                a[mi][2] = __float_as_uint(A[mr * 20 + kk + 4]);
                a[mi][3] = __float_as_uint(A[(mr + 8) * 20 + kk + 4]);
            }
            #pragma unroll
            for (int ni = 0; ni < 2; ni++) {
                int nc = wn * 16 + ni * 8 + (lane >> 2);
                bf[ni][0] = __float_as_uint(Bp[kk * 68 + nc]);
                bf[ni][1] = __float_as_uint(Bp[(kk + 4) * 68 + nc]);
            }
            #pragma unroll
            for (int mi = 0; mi < 4; mi++)
                #pragma unroll
                for (int ni = 0; ni < 2; ni++)
                    mma_tf32(c[mi][ni], a[mi], bf[ni]);
        }
        __syncthreads();
    }

    #pragma unroll
    for (int mi = 0; mi < 4; mi++)
        #pragma unroll
        for (int ni = 0; ni < 2; ni++)
            #pragma unroll
            for (int r = 0; r < 4; r++) {
                int row = byr * 128 + wm * 64 + mi * 16 + (lane >> 2) + ((r >> 1) << 3);
                int col = c0 + wn * 16 + ni * 8 + ((lane & 3) << 1) + (r & 1);
                g_P[(size_t)row * PC + col] = c[mi][ni][r];
            }
}

// ---------------- kernel: H2^T fp16 from g_P (smem transpose) ----------------
__global__ __launch_bounds__(256) void k_h2t() {
    __shared__ __half sh[64][72];
    int r0 = blockIdx.x * 64;
    int t = threadIdx.x;
    int r = t >> 2, cq = (t & 3) * 16;
    const float* src = g_P + (size_t)(r0 + r) * PC + 128 + cq;
    #pragma unroll
    for (int q = 0; q < 4; ++q) {
        float4 v = *(const float4*)(src + q * 4);
        sh[r][cq + q * 4 + 0] = __float2half_rn(v.x);
        sh[r][cq + q * 4 + 1] = __float2half_rn(v.y);
        sh[r][cq + q * 4 + 2] = __float2half_rn(v.z);
        sh[r][cq + q * 4 + 3] = __float2half_rn(v.w);
    }
    __syncthreads();
    int c = t >> 2, rq = (t & 3) * 16;
    int b = r0 >> 12, n0 = r0 & (NN - 1);
    __half* dst = g_H2T + ((size_t)b * DOUT + c) * NN + n0 + rq;
    #pragma unroll
    for (int q = 0; q < 16; ++q) dst[q] = sh[rq + q][c];
}

// ---------------- kernel: SpMM fp16, split-K x4, 2-stage cp.async ------------
__global__ __launch_bounds__(256, 4) void k_spmm16(int stage) {
    __shared__ uint32_t sm[2 * 2560];     // per stage: A 64*20 + B 64*20 u32
    int rt = blockIdx.x, b = blockIdx.y;
    int type = blockIdx.z >> 2, sp = blockIdx.z & 3;
    int mbase = sp * (NN / 4);
    const __half* Km = (type ? g_Kw : g_Kb) + (size_t)b * NN * NN;
    const __half* Ht;
    float* Out;
    if (stage == 1) {
        Ht = g_H2T + (size_t)b * DOUT * NN;
        float* o4[4] = {g_t0, g_t1, g_t2, g_t3};
        Out = o4[sp] + ((size_t)type * BB + b) * NN * DOUT;
    } else {
        Ht = g_tT + (size_t)(type * BB + b) * DOUT * NN;
        float* o4[4] = {g_g0, g_g1, g_g2, g_g3};
        Out = o4[sp] + ((size_t)type * BB + b) * NN * DOUT;
    }
    int tid = threadIdx.x, lane = tid & 31, wid = tid >> 5;
    int wm = wid & 3, wn = wid >> 2;
    uint32_t sb = (uint32_t)__cvta_generic_to_shared(sm);

    float c[4][4];
    #pragma unroll
    for (int i = 0; i < 4; i++)
        #pragma unroll
        for (int r = 0; r < 4; r++) c[i][r] = 0.f;

    int arow = tid >> 2, apart = tid & 3;
    const int NCH = 32;
    {
        uint32_t sA = sb, sB = sb + 1280 * 4;
        cpa16(sA + (arow * 20 + apart * 4) * 4, Km + (size_t)(rt * 64 + arow) * NN + mbase + apart * 8);
        cpa16(sB + (arow * 20 + apart * 4) * 4, Ht + (size_t)arow * NN + mbase + apart * 8);
    }
    CP_COMMIT();

    #pragma unroll 1
    for (int cc = 0; cc < NCH; ++cc) {
        if (cc + 1 < NCH) {
            int s = (cc + 1) & 1, m0 = mbase + (cc + 1) * 32;
            uint32_t sA = sb + (s * 2560) * 4, sB = sA + 1280 * 4;
            cpa16(sA + (arow * 20 + apart * 4) * 4, Km + (size_t)(rt * 64 + arow) * NN + m0 + apart * 8);
            cpa16(sB + (arow * 20 + apart * 4) * 4, Ht + (size_t)arow * NN + m0 + apart * 8);
        }
        CP_COMMIT();
        CP_WAIT1();
        __syncthreads();
        const uint32_t* A  = sm + (cc & 1) * 2560;
        const uint32_t* Bp = A + 1280;
        int mr = wm * 16 + (lane >> 2);
        #pragma unroll
        for (int ks = 0; ks < 2; ++ks) {
            int kb = ks * 8 + (lane & 3);
            uint32_t a[4];
            a[0] = A[mr * 20 + kb];
            a[1] = A[(mr + 8) * 20 + kb];
            a[2] = A[mr * 20 + kb + 4];
            a[3] = A[(mr + 8) * 20 + kb + 4];
            #pragma unroll
            for (int ni = 0; ni < 4; ni++) {
                int nc = wn * 32 + ni * 8 + (lane >> 2);
                uint32_t bf[2];
                bf[0] = Bp[nc * 20 + kb];
                bf[1] = Bp[nc * 20 + kb + 4];
                mma_f16(c[ni], a, bf);
            }
        }
        __syncthreads();
    }

    #pragma unroll
    for (int ni = 0; ni < 4; ni++)
        #pragma unroll
        for (int r = 0; r < 4; r++) {
            int row = rt * 64 + wm * 16 + (lane >> 2) + ((r >> 1) << 3);
            int col = wn * 32 + ni * 8 + ((lane & 3) << 1) + (r & 1);
            Out[(size_t)row * DOUT + col] = c[ni][r];
        }
}

// ---------------- combine stage-1 partials + h1, write fp16 transposed -------
__global__ __launch_bounds__(256) void k_comb1t() {
    __shared__ __half sh[64][72];
    int n0 = blockIdx.x * 64, tb = blockIdx.y;
    int b = tb & 1;
    int t = threadIdx.x;
    int r = t >> 2, cq = (t & 3) * 16;
    size_t base = ((size_t)tb * NN + n0 + r) * DOUT + cq;
    const float* P = g_P + ((size_t)b * NN + n0 + r) * PC + 64 + cq;
    #pragma unroll
    for (int q = 0; q < 4; ++q) {
        float4 v0 = *(const float4*)(g_t0 + base + q * 4);
        float4 v1 = *(const float4*)(g_t1 + base + q * 4);
        float4 v2 = *(const float4*)(g_t2 + base + q * 4);
        float4 v3 = *(const float4*)(g_t3 + base + q * 4);
        float4 vp = *(const float4*)(P + q * 4);
        sh[r][cq + q * 4 + 0] = __float2half_rn((v0.x + v1.x) + (v2.x + v3.x) + vp.x);
        sh[r][cq + q * 4 + 1] = __float2half_rn((v0.y + v1.y) + (v2.y + v3.y) + vp.y);
        sh[r][cq + q * 4 + 2] = __float2half_rn((v0.z + v1.z) + (v2.z + v3.z) + vp.z);
        sh[r][cq + q * 4 + 3] = __float2half_rn((v0.w + v1.w) + (v2.w + v3.w) + vp.w);
    }
    __syncthreads();
    int c = t >> 2, rq = (t & 3) * 16;
    __half* dst = g_tT + ((size_t)tb * DOUT + c) * NN + n0 + rq;
    #pragma unroll
    for (int q = 0; q < 16; ++q) dst[q] = sh[rq + q][c];
}

// ---------------- final epilogue ---------------------------------------------
__global__ void k_final(const float* __restrict__ b_lin, float* __restrict__ out) {
    int idx = blockIdx.x * 256 + threadIdx.x;
    int cidx = idx & 127;
    int n = (idx >> 7) & (NN - 1);
    int b = idx >> 19;
    int half = cidx >> 6, cc = cidx & 63;
    const float* P = g_P + ((size_t)b * NN + n) * PC;
    size_t gi = (((size_t)half * BB + b) * NN + n) * DOUT + cc;
    float g = (g_g0[gi] + g_g1[gi]) + (g_g2[gi] + g_g3[gi]);
    float v = P[cc] + g + P[192 + cidx] + b_lin[cidx];
    out[idx] = fmaxf(v, 0.f);
}

// ---------------- launch -----------------------------------------------------
extern "C" void kernel_launch(void* const* d_in, const int* in_sizes, int n_in,
                              void* d_out, int out_size) {
    const float* x  = (const float*)d_in[0];
    const float* Wk = (const float*)d_in[1];
    const float* Wl = (const float*)d_in[2];
    const float* bl = (const float*)d_in[3];
    float* out = (float*)d_out;

    k_xcvt<<<(BB * NN * DD / 4) / 256, 256>>>(x);
    k_sqnorm<<<BB * NN / 8, 256>>>(x);
    k_wcat<<<(DD * PC + 255) / 256, 256>>>(Wk, Wl);
    k_gram<<<dim3(1056, BB), 256>>>();
    k_proj<<<dim3(PC / 64, (BB * NN) / 128), 256>>>();
    k_h2t<<<(BB * NN) / 64, 256>>>();
    k_spmm16<<<dim3(NN / 64, BB, 8), 256>>>(1);
    k_comb1t<<<dim3(NN / 64, 4), 256>>>();
    k_spmm16<<<dim3(NN / 64, BB, 8), 256>>>(2);
    k_final<<<(BB * NN * 128) / 256, 256>>>(bl, out);
}

// round 14
// speedup vs baseline: 1.8355x; 1.1452x over previous
#include <cuda_runtime.h>
#include <cuda_fp16.h>
#include <cstdint>

#define BB   2
#define NN   4096
#define DD   256
#define PC   320     // 3*64 (Wk) + 128 (W_lin)
#define DOUT 64

// ---------------- scratch ---------------------------------------------------
__device__ __half g_Kb[(size_t)BB * NN * NN];      // fp16 kernel matrices
__device__ __half g_Kw[(size_t)BB * NN * NN];
__device__ float  g_sq[BB * NN];
__device__ float  g_Wcat[DD * PC];                 // tf32-rounded
__device__ float  g_Xt[(size_t)BB * NN * DD];      // tf32-rounded x (for proj)
__device__ __half g_Xh[(size_t)BB * NN * DD];      // fp16 x (for gram)
__device__ float  g_P[(size_t)BB * NN * PC];       // fp32 x@Wcat
__device__ __half g_H2T[(size_t)BB * DOUT * NN];   // h2^T, fp16 [b][col][row]
__device__ __half g_tT[(size_t)4 * DOUT * NN];     // stage-1^T, fp16 [tb][col][row]
__device__ float  g_t0[(size_t)2 * BB * NN * DOUT];
__device__ float  g_t1[(size_t)2 * BB * NN * DOUT];
__device__ float  g_t2[(size_t)2 * BB * NN * DOUT];
__device__ float  g_t3[(size_t)2 * BB * NN * DOUT];
__device__ float  g_g0[(size_t)2 * BB * NN * DOUT];
__device__ float  g_g1[(size_t)2 * BB * NN * DOUT];
__device__ float  g_g2[(size_t)2 * BB * NN * DOUT];
__device__ float  g_g3[(size_t)2 * BB * NN * DOUT];

// ---------------- helpers ---------------------------------------------------
__device__ __forceinline__ uint32_t f2tf(float f) {
    uint32_t u;
    asm volatile("cvt.rna.tf32.f32 %0, %1;" : "=r"(u) : "f"(f));
    return u;
}

__device__ __forceinline__ void mma_tf32(float c[4], const uint32_t a[4], const uint32_t b[2]) {
    asm volatile(
        "mma.sync.aligned.m16n8k8.row.col.f32.tf32.tf32.f32 "
        "{%0,%1,%2,%3}, {%4,%5,%6,%7}, {%8,%9}, {%0,%1,%2,%3};\n"
        : "+f"(c[0]), "+f"(c[1]), "+f"(c[2]), "+f"(c[3])
        : "r"(a[0]), "r"(a[1]), "r"(a[2]), "r"(a[3]),
          "r"(b[0]), "r"(b[1]));
}

__device__ __forceinline__ void mma_f16(float c[4], const uint32_t a[4], const uint32_t b[2]) {
    asm volatile(
        "mma.sync.aligned.m16n8k16.row.col.f32.f16.f16.f32 "
        "{%0,%1,%2,%3}, {%4,%5,%6,%7}, {%8,%9}, {%0,%1,%2,%3};\n"
        : "+f"(c[0]), "+f"(c[1]), "+f"(c[2]), "+f"(c[3])
        : "r"(a[0]), "r"(a[1]), "r"(a[2]), "r"(a[3]),
          "r"(b[0]), "r"(b[1]));
}

__device__ __forceinline__ void ldsm_x4(uint32_t& r0, uint32_t& r1, uint32_t& r2, uint32_t& r3,
                                        uint32_t addr) {
    asm volatile("ldmatrix.sync.aligned.m8n8.x4.shared.b16 {%0,%1,%2,%3}, [%4];"
                 : "=r"(r0), "=r"(r1), "=r"(r2), "=r"(r3) : "r"(addr));
}

__device__ __forceinline__ void cpa16(uint32_t dst, const void* src) {
    asm volatile("cp.async.cg.shared.global [%0], [%1], 16;\n" :: "r"(dst), "l"(src));
}
#define CP_COMMIT() asm volatile("cp.async.commit_group;\n" ::: "memory")
#define CP_WAIT1()  asm volatile("cp.async.wait_group 1;\n" ::: "memory")

// Closed-form cubic B-spline on uniform knots {0,.25,.5,.75,1} (== reference).
__device__ __forceinline__ float b3fold(float v) {
    float outer = v * v * v * (1.f / 6.f);
    float inner = (((-3.f * v + 12.f) * v - 12.f) * v + 4.f) * (1.f / 6.f);
    return (v < 1.f) ? outer : inner;
}
__device__ __forceinline__ float bk_eval(float t) {
    float v = 2.f - fabsf(4.f * t - 2.f);
    return b3fold(v);
}
__device__ __forceinline__ float wk_eval(float t) {
    float sg = 8.f * t;
    bool lo = (sg < 4.f);
    float sp = lo ? sg : sg - 4.f;
    float v = 2.f - fabsf(sp - 2.f);
    float r = b3fold(v);
    return lo ? r : -r;
}

// ---------------- tiny prep kernels -----------------------------------------
__global__ void k_xcvt(const float* __restrict__ x) {
    int i = blockIdx.x * 256 + threadIdx.x;
    float4 v = ((const float4*)x)[i];
    uint4 o;
    o.x = f2tf(v.x); o.y = f2tf(v.y); o.z = f2tf(v.z); o.w = f2tf(v.w);
    ((uint4*)g_Xt)[i] = o;
    __half2 h0 = __floats2half2_rn(v.x, v.y);
    __half2 h1 = __floats2half2_rn(v.z, v.w);
    uint2 ho;
    ho.x = *(uint32_t*)&h0;
    ho.y = *(uint32_t*)&h1;
    ((uint2*)g_Xh)[i] = ho;
}

__global__ void k_sqnorm(const float* __restrict__ x) {
    int row  = blockIdx.x * 8 + (threadIdx.x >> 5);
    int lane = threadIdx.x & 31;
    const float* xr = x + (size_t)row * DD;
    float s = 0.f;
    #pragma unroll
    for (int i = lane; i < DD; i += 32) { float v = xr[i]; s += v * v; }
    #pragma unroll
    for (int o = 16; o; o >>= 1) s += __shfl_xor_sync(0xffffffffu, s, o);
    if (lane == 0) g_sq[row] = s;
}

__global__ void k_wcat(const float* __restrict__ Wk, const float* __restrict__ Wl) {
    int i = blockIdx.x * 256 + threadIdx.x;
    if (i >= DD * PC) return;
    int d = i / PC, cidx = i % PC;
    float v;
    if (cidx < 192) v = Wk[(size_t)(cidx / 64) * DD * 64 + (size_t)d * 64 + (cidx & 63)];
    else            v = Wl[(size_t)d * 128 + (cidx - 192)];
    g_Wcat[i] = __uint_as_float(f2tf(v));
}

// ---------------- kernel: Gram + spline (fp16 mainloop, ldmatrix) ------------
// Block tile 128(m) x 64(n); 8 warps 4m x 2n, warp tile 32x32.
// KC=32 halves/chunk (64B/row), 8 chunks. Rows padded to 20 u32 (80B).
// smem: 2 stages x (A 128x20 + B 64x20) u32 = 30 KB. 4 blocks/SM.
__global__ __launch_bounds__(256, 4) void k_gram() {
    __shared__ uint32_t sm[2 * 3840];
    int h   = blockIdx.x & 1;
    int idx = blockIdx.x >> 1;
    int b   = blockIdx.y;
    int tj = (int)((sqrtf(8.f * idx + 1.f) - 1.f) * 0.5f);
    while ((tj + 1) * (tj + 2) / 2 <= idx) ++tj;
    while (tj * (tj + 1) / 2 > idx) --tj;
    int ti = idx - tj * (tj + 1) / 2;

    int tid = threadIdx.x, lane = tid & 31, wid = tid >> 5;
    int wm = wid & 3, wn = wid >> 2;
    const __half* Xa = g_Xh + ((size_t)b * NN + (size_t)ti * 128) * DD;
    const __half* Xb = g_Xh + ((size_t)b * NN + (size_t)tj * 128 + (size_t)h * 64) * DD;
    uint32_t sb = (uint32_t)__cvta_generic_to_shared(sm);

    float c[2][4][4];
    #pragma unroll
    for (int i = 0; i < 2; i++)
        #pragma unroll
        for (int j = 0; j < 4; j++)
            #pragma unroll
            for (int r = 0; r < 4; r++) c[i][j][r] = 0.f;

    // cp.async layout indices
    int arow_l = tid >> 2,         apart_l = tid & 3;
    int arow_h = (256 + tid) >> 2, apart_h = (256 + tid) & 3;
    int brow   = tid >> 2,         bpart   = tid & 3;

    // ldmatrix per-thread byte offsets (within a stage)
    // A x4 for (mi,ks): row = wm*32 + mi*16 + (lane&15), col16 = (lane>>4)
    uint32_t aRowOff = (uint32_t)(wm * 32 + (lane & 15)) * 80 + (uint32_t)(lane >> 4) * 16;
    // B x4 for (g,ks): row = wn*32 + g*16 + (lane>>4)*8 + (lane&7), col16 = (lane>>3)&1
    uint32_t bRowOff = (uint32_t)(wn * 32 + ((lane >> 4) << 3) + (lane & 7)) * 80
                     + (uint32_t)((lane >> 3) & 1) * 16;

    {   // prologue: chunk 0 -> stage 0
        uint32_t sA = sb, sB = sb + 2560 * 4;
        cpa16(sA + (arow_l * 20 + apart_l * 4) * 4, Xa + (size_t)arow_l * DD + apart_l * 8);
        cpa16(sA + (arow_h * 20 + apart_h * 4) * 4, Xa + (size_t)arow_h * DD + apart_h * 8);
        cpa16(sB + (brow * 20 + bpart * 4) * 4, Xb + (size_t)brow * DD + bpart * 8);
    }
    CP_COMMIT();

    for (int cc = 0; cc < 8; ++cc) {
        if (cc + 1 < 8) {
            int s = (cc + 1) & 1, k0 = (cc + 1) * 32;
            uint32_t sA = sb + (s * 3840) * 4, sB = sA + 2560 * 4;
            cpa16(sA + (arow_l * 20 + apart_l * 4) * 4, Xa + (size_t)arow_l * DD + k0 + apart_l * 8);
            cpa16(sA + (arow_h * 20 + apart_h * 4) * 4, Xa + (size_t)arow_h * DD + k0 + apart_h * 8);
            cpa16(sB + (brow * 20 + bpart * 4) * 4, Xb + (size_t)brow * DD + k0 + bpart * 8);
        }
        CP_COMMIT();
        CP_WAIT1();
        __syncthreads();
        uint32_t As = sb + (cc & 1) * 3840 * 4;
        uint32_t Bs = As + 2560 * 4;
        #pragma unroll
        for (int ks = 0; ks < 2; ++ks) {
            uint32_t a[2][4], bf[4][2];
            #pragma unroll
            for (int mi = 0; mi < 2; mi++)
                ldsm_x4(a[mi][0], a[mi][1], a[mi][2], a[mi][3],
                        As + aRowOff + (uint32_t)mi * 16 * 80 + (uint32_t)ks * 32);
            ldsm_x4(bf[0][0], bf[0][1], bf[1][0], bf[1][1],
                    Bs + bRowOff + (uint32_t)ks * 32);
            ldsm_x4(bf[2][0], bf[2][1], bf[3][0], bf[3][1],
                    Bs + bRowOff + 16 * 80 + (uint32_t)ks * 32);
            #pragma unroll
            for (int mi = 0; mi < 2; mi++)
                #pragma unroll
                for (int ni = 0; ni < 4; ni++)
                    mma_f16(c[mi][ni], a[mi], bf[ni]);
        }
        __syncthreads();
    }

    __half* Kb = g_Kb + (size_t)b * NN * NN;
    __half* Kw = g_Kw + (size_t)b * NN * NN;
    const float* sq = g_sq + b * NN;
    int i0 = ti * 128 + wm * 32, j0 = tj * 128 + h * 64 + wn * 32;
    bool mir = (ti != tj);
    #pragma unroll
    for (int mi = 0; mi < 2; mi++)
        #pragma unroll
        for (int ni = 0; ni < 4; ni++)
            #pragma unroll
            for (int rh = 0; rh < 2; rh++) {
                int i = i0 + mi * 16 + (lane >> 2) + rh * 8;
                int j = j0 + ni * 8 + ((lane & 3) << 1);
                float sqi = sq[i];
                float bkv[2], wkv[2];
                #pragma unroll
                for (int rl = 0; rl < 2; rl++) {
                    float d2 = sqi + sq[j + rl] - 2.f * c[mi][ni][rh * 2 + rl];
                    d2 = fmaxf(d2, 0.f);
                    float t = __expf(d2 * (-1.f / 512.f));
                    bkv[rl] = bk_eval(t);
                    wkv[rl] = wk_eval(t);
                }
                __half2 bh = __floats2half2_rn(bkv[0], bkv[1]);
                __half2 wh = __floats2half2_rn(wkv[0], wkv[1]);
                *(__half2*)(Kb + (size_t)i * NN + j) = bh;
                *(__half2*)(Kw + (size_t)i * NN + j) = wh;
                if (mir) {
                    Kb[(size_t)j * NN + i]       = __low2half(bh);
                    Kb[(size_t)(j + 1) * NN + i] = __high2half(bh);
                    Kw[(size_t)j * NN + i]       = __low2half(wh);
                    Kw[(size_t)(j + 1) * NN + i] = __high2half(wh);
                }
            }
}

// ---------------- kernel: projection P = x @ Wcat (tf32, unchanged) ----------
__global__ __launch_bounds__(256) void k_proj() {
    __shared__ float sm[2 * 3648];
    int c0 = blockIdx.x * 64, byr = blockIdx.y;
    int tid = threadIdx.x, lane = tid & 31, wid = tid >> 5;
    int wm = wid & 1, wn = wid >> 1;
    const float* Xa = g_Xt + (size_t)byr * 128 * DD;
    uint32_t sb = (uint32_t)__cvta_generic_to_shared(sm);

    float c[4][2][4];
    #pragma unroll
    for (int i = 0; i < 4; i++)
        #pragma unroll
        for (int j = 0; j < 2; j++)
            #pragma unroll
            for (int r = 0; r < 4; r++) c[i][j][r] = 0.f;

    {
        uint32_t sA = sb, sB = sb + 2560 * 4;
        #pragma unroll
        for (int it = 0; it < 2; ++it) {
            int id = it * 256 + tid;
            int row = id >> 2, part = (id & 3) << 2;
            cpa16(sA + (row * 20 + part) * 4, Xa + (size_t)row * DD + part);
        }
        int kk = tid >> 4, cq = (tid & 15) << 2;
        cpa16(sB + (kk * 68 + cq) * 4, g_Wcat + (size_t)kk * PC + c0 + cq);
    }
    CP_COMMIT();

    for (int cc = 0; cc < 16; ++cc) {
        if (cc + 1 < 16) {
            int s = (cc + 1) & 1, k0 = (cc + 1) * 16;
            uint32_t sA = sb + (s * 3648) * 4, sB = sA + 2560 * 4;
            #pragma unroll
            for (int it = 0; it < 2; ++it) {
                int id = it * 256 + tid;
                int row = id >> 2, part = (id & 3) << 2;
                cpa16(sA + (row * 20 + part) * 4, Xa + (size_t)row * DD + k0 + part);
            }
            int kk = tid >> 4, cq = (tid & 15) << 2;
            cpa16(sB + (kk * 68 + cq) * 4, g_Wcat + (size_t)(k0 + kk) * PC + c0 + cq);
        }
        CP_COMMIT();
        CP_WAIT1();
        __syncthreads();
        const float* A  = sm + (cc & 1) * 3648;
        const float* Bp = A + 2560;
        #pragma unroll
        for (int ks = 0; ks < 2; ++ks) {
            int kk = ks * 8 + (lane & 3);
            uint32_t a[4][4], bf[2][2];
            #pragma unroll
            for (int mi = 0; mi < 4; mi++) {
                int mr = wm * 64 + mi * 16 + (lane >> 2);
                a[mi][0] = __float_as_uint(A[mr * 20 + kk]);
                a[mi][1] = __float_as_uint(A[(mr + 8) * 20 + kk]);
                a[mi][2] = __float_as_uint(A[mr * 20 + kk + 4]);
                a[mi][3] = __float_as_uint(A[(mr + 8) * 20 + kk + 4]);
            }
            #pragma unroll
            for (int ni = 0; ni < 2; ni++) {
                int nc = wn * 16 + ni * 8 + (lane >> 2);
                bf[ni][0] = __float_as_uint(Bp[kk * 68 + nc]);
                bf[ni][1] = __float_as_uint(Bp[(kk + 4) * 68 + nc]);
            }
            #pragma unroll
            for (int mi = 0; mi < 4; mi++)
                #pragma unroll
                for (int ni = 0; ni < 2; ni++)
                    mma_tf32(c[mi][ni], a[mi], bf[ni]);
        }
        __syncthreads();
    }

    #pragma unroll
    for (int mi = 0; mi < 4; mi++)
        #pragma unroll
        for (int ni = 0; ni < 2; ni++)
            #pragma unroll
            for (int r = 0; r < 4; r++) {
                int row = byr * 128 + wm * 64 + mi * 16 + (lane >> 2) + ((r >> 1) << 3);
                int col = c0 + wn * 16 + ni * 8 + ((lane & 3) << 1) + (r & 1);
                g_P[(size_t)row * PC + col] = c[mi][ni][r];
            }
}

// ---------------- kernel: H2^T fp16 from g_P (smem transpose) ----------------
__global__ __launch_bounds__(256) void k_h2t() {
    __shared__ __half sh[64][72];
    int r0 = blockIdx.x * 64;
    int t = threadIdx.x;
    int r = t >> 2, cq = (t & 3) * 16;
    const float* src = g_P + (size_t)(r0 + r) * PC + 128 + cq;
    #pragma unroll
    for (int q = 0; q < 4; ++q) {
        float4 v = *(const float4*)(src + q * 4);
        sh[r][cq + q * 4 + 0] = __float2half_rn(v.x);
        sh[r][cq + q * 4 + 1] = __float2half_rn(v.y);
        sh[r][cq + q * 4 + 2] = __float2half_rn(v.z);
        sh[r][cq + q * 4 + 3] = __float2half_rn(v.w);
    }
    __syncthreads();
    int c = t >> 2, rq = (t & 3) * 16;
    int b = r0 >> 12, n0 = r0 & (NN - 1);
    __half* dst = g_H2T + ((size_t)b * DOUT + c) * NN + n0 + rq;
    #pragma unroll
    for (int q = 0; q < 16; ++q) dst[q] = sh[rq + q][c];
}

// ---------------- kernel: SpMM fp16, split-K x4, ldmatrix --------------------
__global__ __launch_bounds__(256, 4) void k_spmm16(int stage) {
    __shared__ uint32_t sm[2 * 2560];     // per stage: A 64*20 + B 64*20 u32
    int rt = blockIdx.x, b = blockIdx.y;
    int type = blockIdx.z >> 2, sp = blockIdx.z & 3;
    int mbase = sp * (NN / 4);
    const __half* Km = (type ? g_Kw : g_Kb) + (size_t)b * NN * NN;
    const __half* Ht;
    float* Out;
    if (stage == 1) {
        Ht = g_H2T + (size_t)b * DOUT * NN;
        float* o4[4] = {g_t0, g_t1, g_t2, g_t3};
        Out = o4[sp] + ((size_t)type * BB + b) * NN * DOUT;
    } else {
        Ht = g_tT + (size_t)(type * BB + b) * DOUT * NN;
        float* o4[4] = {g_g0, g_g1, g_g2, g_g3};
        Out = o4[sp] + ((size_t)type * BB + b) * NN * DOUT;
    }
    int tid = threadIdx.x, lane = tid & 31, wid = tid >> 5;
    int wm = wid & 3, wn = wid >> 2;
    uint32_t sb = (uint32_t)__cvta_generic_to_shared(sm);

    float c[4][4];
    #pragma unroll
    for (int i = 0; i < 4; i++)
        #pragma unroll
        for (int r = 0; r < 4; r++) c[i][r] = 0.f;

    int arow = tid >> 2, apart = tid & 3;
    // ldmatrix offsets (within stage)
    uint32_t aRowOff = (uint32_t)(wm * 16 + (lane & 15)) * 80 + (uint32_t)(lane >> 4) * 16;
    uint32_t bRowOff = (uint32_t)(wn * 32 + ((lane >> 4) << 3) + (lane & 7)) * 80
                     + (uint32_t)((lane >> 3) & 1) * 16;

    const int NCH = 32;
    {
        uint32_t sA = sb, sB = sb + 1280 * 4;
        cpa16(sA + (arow * 20 + apart * 4) * 4, Km + (size_t)(rt * 64 + arow) * NN + mbase + apart * 8);
        cpa16(sB + (arow * 20 + apart * 4) * 4, Ht + (size_t)arow * NN + mbase + apart * 8);
    }
    CP_COMMIT();

    #pragma unroll 1
    for (int cc = 0; cc < NCH; ++cc) {
        if (cc + 1 < NCH) {
            int s = (cc + 1) & 1, m0 = mbase + (cc + 1) * 32;
            uint32_t sA = sb + (s * 2560) * 4, sB = sA + 1280 * 4;
            cpa16(sA + (arow * 20 + apart * 4) * 4, Km + (size_t)(rt * 64 + arow) * NN + m0 + apart * 8);
            cpa16(sB + (arow * 20 + apart * 4) * 4, Ht + (size_t)arow * NN + m0 + apart * 8);
        }
        CP_COMMIT();
        CP_WAIT1();
        __syncthreads();
        uint32_t As = sb + (cc & 1) * 2560 * 4;
        uint32_t Bs = As + 1280 * 4;
        #pragma unroll
        for (int ks = 0; ks < 2; ++ks) {
            uint32_t a[4], bf[4][2];
            ldsm_x4(a[0], a[1], a[2], a[3], As + aRowOff + (uint32_t)ks * 32);
            ldsm_x4(bf[0][0], bf[0][1], bf[1][0], bf[1][1], Bs + bRowOff + (uint32_t)ks * 32);
            ldsm_x4(bf[2][0], bf[2][1], bf[3][0], bf[3][1], Bs + bRowOff + 16 * 80 + (uint32_t)ks * 32);
            #pragma unroll
            for (int ni = 0; ni < 4; ni++)
                mma_f16(c[ni], a, bf[ni]);
        }
        __syncthreads();
    }

    #pragma unroll
    for (int ni = 0; ni < 4; ni++)
        #pragma unroll
        for (int r = 0; r < 4; r++) {
            int row = rt * 64 + wm * 16 + (lane >> 2) + ((r >> 1) << 3);
            int col = wn * 32 + ni * 8 + ((lane & 3) << 1) + (r & 1);
            Out[(size_t)row * DOUT + col] = c[ni][r];
        }
}

// ---------------- combine stage-1 partials + h1, write fp16 transposed -------
__global__ __launch_bounds__(256) void k_comb1t() {
    __shared__ __half sh[64][72];
    int n0 = blockIdx.x * 64, tb = blockIdx.y;
    int b = tb & 1;
    int t = threadIdx.x;
    int r = t >> 2, cq = (t & 3) * 16;
    size_t base = ((size_t)tb * NN + n0 + r) * DOUT + cq;
    const float* P = g_P + ((size_t)b * NN + n0 + r) * PC + 64 + cq;
    #pragma unroll
    for (int q = 0; q < 4; ++q) {
        float4 v0 = *(const float4*)(g_t0 + base + q * 4);
        float4 v1 = *(const float4*)(g_t1 + base + q * 4);
        float4 v2 = *(const float4*)(g_t2 + base + q * 4);
        float4 v3 = *(const float4*)(g_t3 + base + q * 4);
        float4 vp = *(const float4*)(P + q * 4);
        sh[r][cq + q * 4 + 0] = __float2half_rn((v0.x + v1.x) + (v2.x + v3.x) + vp.x);
        sh[r][cq + q * 4 + 1] = __float2half_rn((v0.y + v1.y) + (v2.y + v3.y) + vp.y);
        sh[r][cq + q * 4 + 2] = __float2half_rn((v0.z + v1.z) + (v2.z + v3.z) + vp.z);
        sh[r][cq + q * 4 + 3] = __float2half_rn((v0.w + v1.w) + (v2.w + v3.w) + vp.w);
    }
    __syncthreads();
    int c = t >> 2, rq = (t & 3) * 16;
    __half* dst = g_tT + ((size_t)tb * DOUT + c) * NN + n0 + rq;
    #pragma unroll
    for (int q = 0; q < 16; ++q) dst[q] = sh[rq + q][c];
}

// ---------------- final epilogue ---------------------------------------------
__global__ void k_final(const float* __restrict__ b_lin, float* __restrict__ out) {
    int idx = blockIdx.x * 256 + threadIdx.x;
    int cidx = idx & 127;
    int n = (idx >> 7) & (NN - 1);
    int b = idx >> 19;
    int half = cidx >> 6, cc = cidx & 63;
    const float* P = g_P + ((size_t)b * NN + n) * PC;
    size_t gi = (((size_t)half * BB + b) * NN + n) * DOUT + cc;
    float g = (g_g0[gi] + g_g1[gi]) + (g_g2[gi] + g_g3[gi]);
    float v = P[cc] + g + P[192 + cidx] + b_lin[cidx];
    out[idx] = fmaxf(v, 0.f);
}

// ---------------- launch -----------------------------------------------------
extern "C" void kernel_launch(void* const* d_in, const int* in_sizes, int n_in,
                              void* d_out, int out_size) {
    const float* x  = (const float*)d_in[0];
    const float* Wk = (const float*)d_in[1];
    const float* Wl = (const float*)d_in[2];
    const float* bl = (const float*)d_in[3];
    float* out = (float*)d_out;

    k_xcvt<<<(BB * NN * DD / 4) / 256, 256>>>(x);
    k_sqnorm<<<BB * NN / 8, 256>>>(x);
    k_wcat<<<(DD * PC + 255) / 256, 256>>>(Wk, Wl);
    k_gram<<<dim3(1056, BB), 256>>>();
    k_proj<<<dim3(PC / 64, (BB * NN) / 128), 256>>>();
    k_h2t<<<(BB * NN) / 64, 256>>>();
    k_spmm16<<<dim3(NN / 64, BB, 8), 256>>>(1);
    k_comb1t<<<dim3(NN / 64, 4), 256>>>();
    k_spmm16<<<dim3(NN / 64, BB, 8), 256>>>(2);
    k_final<<<(BB * NN * 128) / 256, 256>>>(bl, out);
}

// round 15
// speedup vs baseline: 2.0565x; 1.1204x over previous
#include <cuda_runtime.h>
#include <cuda_fp16.h>
#include <cstdint>

#define BB   2
#define NN   4096
#define DD   256
#define PC   320     // 3*64 (Wk) + 128 (W_lin)
#define DOUT 64

// ---------------- scratch ---------------------------------------------------
__device__ __half g_Kb[(size_t)BB * NN * NN];      // fp16 kernel matrices
__device__ __half g_Kw[(size_t)BB * NN * NN];
__device__ float  g_sq[BB * NN];
__device__ float  g_Wcat[DD * PC];                 // tf32-rounded
__device__ float  g_Xt[(size_t)BB * NN * DD];      // tf32-rounded x (for proj)
__device__ __half g_Xh[(size_t)BB * NN * DD];      // fp16 x (for gram)
__device__ float  g_P[(size_t)BB * NN * PC];       // fp32 x@Wcat
__device__ __half g_H2T[(size_t)BB * DOUT * NN];   // h2^T, fp16 [b][col][row]
__device__ __half g_tT[(size_t)4 * DOUT * NN];     // stage-1^T, fp16 [tb][col][row]
__device__ float  g_t0[(size_t)2 * BB * NN * DOUT];
__device__ float  g_t1[(size_t)2 * BB * NN * DOUT];
__device__ float  g_t2[(size_t)2 * BB * NN * DOUT];
__device__ float  g_t3[(size_t)2 * BB * NN * DOUT];
__device__ float  g_g0[(size_t)2 * BB * NN * DOUT];
__device__ float  g_g1[(size_t)2 * BB * NN * DOUT];
__device__ float  g_g2[(size_t)2 * BB * NN * DOUT];
__device__ float  g_g3[(size_t)2 * BB * NN * DOUT];

// ---------------- helpers ---------------------------------------------------
__device__ __forceinline__ uint32_t f2tf(float f) {
    uint32_t u;
    asm volatile("cvt.rna.tf32.f32 %0, %1;" : "=r"(u) : "f"(f));
    return u;
}

__device__ __forceinline__ void mma_tf32(float c[4], const uint32_t a[4], const uint32_t b[2]) {
    asm volatile(
        "mma.sync.aligned.m16n8k8.row.col.f32.tf32.tf32.f32 "
        "{%0,%1,%2,%3}, {%4,%5,%6,%7}, {%8,%9}, {%0,%1,%2,%3};\n"
        : "+f"(c[0]), "+f"(c[1]), "+f"(c[2]), "+f"(c[3])
        : "r"(a[0]), "r"(a[1]), "r"(a[2]), "r"(a[3]),
          "r"(b[0]), "r"(b[1]));
}

__device__ __forceinline__ void mma_f16(float c[4], const uint32_t a[4], const uint32_t b[2]) {
    asm volatile(
        "mma.sync.aligned.m16n8k16.row.col.f32.f16.f16.f32 "
        "{%0,%1,%2,%3}, {%4,%5,%6,%7}, {%8,%9}, {%0,%1,%2,%3};\n"
        : "+f"(c[0]), "+f"(c[1]), "+f"(c[2]), "+f"(c[3])
        : "r"(a[0]), "r"(a[1]), "r"(a[2]), "r"(a[3]),
          "r"(b[0]), "r"(b[1]));
}

__device__ __forceinline__ void ldsm_x4(uint32_t& r0, uint32_t& r1, uint32_t& r2, uint32_t& r3,
                                        uint32_t addr) {
    asm volatile("ldmatrix.sync.aligned.m8n8.x4.shared.b16 {%0,%1,%2,%3}, [%4];"
                 : "=r"(r0), "=r"(r1), "=r"(r2), "=r"(r3) : "r"(addr));
}

__device__ __forceinline__ void cpa16(uint32_t dst, const void* src) {
    asm volatile("cp.async.cg.shared.global [%0], [%1], 16;\n" :: "r"(dst), "l"(src));
}
#define CP_COMMIT() asm volatile("cp.async.commit_group;\n" ::: "memory")
#define CP_WAIT1()  asm volatile("cp.async.wait_group 1;\n" ::: "memory")

// Closed-form cubic B-spline on uniform knots {0,.25,.5,.75,1} (== reference).
__device__ __forceinline__ float b3fold(float v) {
    float outer = v * v * v * (1.f / 6.f);
    float inner = (((-3.f * v + 12.f) * v - 12.f) * v + 4.f) * (1.f / 6.f);
    return (v < 1.f) ? outer : inner;
}
__device__ __forceinline__ float bk_eval(float t) {
    float v = 2.f - fabsf(4.f * t - 2.f);
    return b3fold(v);
}
__device__ __forceinline__ float wk_eval(float t) {
    float sg = 8.f * t;
    bool lo = (sg < 4.f);
    float sp = lo ? sg : sg - 4.f;
    float v = 2.f - fabsf(sp - 2.f);
    float r = b3fold(v);
    return lo ? r : -r;
}

// ---------------- tiny prep kernels -----------------------------------------
__global__ void k_xcvt(const float* __restrict__ x) {
    int i = blockIdx.x * 256 + threadIdx.x;
    float4 v = ((const float4*)x)[i];
    uint4 o;
    o.x = f2tf(v.x); o.y = f2tf(v.y); o.z = f2tf(v.z); o.w = f2tf(v.w);
    ((uint4*)g_Xt)[i] = o;
    __half2 h0 = __floats2half2_rn(v.x, v.y);
    __half2 h1 = __floats2half2_rn(v.z, v.w);
    uint2 ho;
    ho.x = *(uint32_t*)&h0;
    ho.y = *(uint32_t*)&h1;
    ((uint2*)g_Xh)[i] = ho;
}

__global__ void k_sqnorm(const float* __restrict__ x) {
    int row  = blockIdx.x * 8 + (threadIdx.x >> 5);
    int lane = threadIdx.x & 31;
    const float* xr = x + (size_t)row * DD;
    float s = 0.f;
    #pragma unroll
    for (int i = lane; i < DD; i += 32) { float v = xr[i]; s += v * v; }
    #pragma unroll
    for (int o = 16; o; o >>= 1) s += __shfl_xor_sync(0xffffffffu, s, o);
    if (lane == 0) g_sq[row] = s;
}

__global__ void k_wcat(const float* __restrict__ Wk, const float* __restrict__ Wl) {
    int i = blockIdx.x * 256 + threadIdx.x;
    if (i >= DD * PC) return;
    int d = i / PC, cidx = i % PC;
    float v;
    if (cidx < 192) v = Wk[(size_t)(cidx / 64) * DD * 64 + (size_t)d * 64 + (cidx & 63)];
    else            v = Wl[(size_t)d * 128 + (cidx - 192)];
    g_Wcat[i] = __uint_as_float(f2tf(v));
}

// ---------------- kernel: Gram + spline (fp16 mainloop, ldmatrix) ------------
// Block tile 128(m) x 64(n); 8 warps 4m x 2n, warp tile 32x32.
// KC=32 halves/chunk, 8 chunks. Rows padded to 20 u32 (80B).
// smem: 2 stages x (A 128x20 + B 64x20) u32 = 30 KB. 4 blocks/SM.
__global__ __launch_bounds__(256, 4) void k_gram() {
    __shared__ uint32_t sm[2 * 3840];
    int h   = blockIdx.x & 1;
    int idx = blockIdx.x >> 1;
    int b   = blockIdx.y;
    int tj = (int)((sqrtf(8.f * idx + 1.f) - 1.f) * 0.5f);
    while ((tj + 1) * (tj + 2) / 2 <= idx) ++tj;
    while (tj * (tj + 1) / 2 > idx) --tj;
    int ti = idx - tj * (tj + 1) / 2;

    int tid = threadIdx.x, lane = tid & 31, wid = tid >> 5;
    int wm = wid & 3, wn = wid >> 2;
    const __half* Xa = g_Xh + ((size_t)b * NN + (size_t)ti * 128) * DD;
    const __half* Xb = g_Xh + ((size_t)b * NN + (size_t)tj * 128 + (size_t)h * 64) * DD;
    uint32_t sb = (uint32_t)__cvta_generic_to_shared(sm);

    float c[2][4][4];
    #pragma unroll
    for (int i = 0; i < 2; i++)
        #pragma unroll
        for (int j = 0; j < 4; j++)
            #pragma unroll
            for (int r = 0; r < 4; r++) c[i][j][r] = 0.f;

    int arow_l = tid >> 2,         apart_l = tid & 3;
    int arow_h = (256 + tid) >> 2, apart_h = (256 + tid) & 3;
    int brow   = tid >> 2,         bpart   = tid & 3;

    uint32_t aRowOff = (uint32_t)(wm * 32 + (lane & 15)) * 80 + (uint32_t)(lane >> 4) * 16;
    uint32_t bRowOff = (uint32_t)(wn * 32 + ((lane >> 4) << 3) + (lane & 7)) * 80
                     + (uint32_t)((lane >> 3) & 1) * 16;

    {   // prologue: chunk 0 -> stage 0
        uint32_t sA = sb, sB = sb + 2560 * 4;
        cpa16(sA + (arow_l * 20 + apart_l * 4) * 4, Xa + (size_t)arow_l * DD + apart_l * 8);
        cpa16(sA + (arow_h * 20 + apart_h * 4) * 4, Xa + (size_t)arow_h * DD + apart_h * 8);
        cpa16(sB + (brow * 20 + bpart * 4) * 4, Xb + (size_t)brow * DD + bpart * 8);
    }
    CP_COMMIT();

    for (int cc = 0; cc < 8; ++cc) {
        if (cc + 1 < 8) {
            int s = (cc + 1) & 1, k0 = (cc + 1) * 32;
            uint32_t sA = sb + (s * 3840) * 4, sB = sA + 2560 * 4;
            cpa16(sA + (arow_l * 20 + apart_l * 4) * 4, Xa + (size_t)arow_l * DD + k0 + apart_l * 8);
            cpa16(sA + (arow_h * 20 + apart_h * 4) * 4, Xa + (size_t)arow_h * DD + k0 + apart_h * 8);
            cpa16(sB + (brow * 20 + bpart * 4) * 4, Xb + (size_t)brow * DD + k0 + bpart * 8);
        }
        CP_COMMIT();
        CP_WAIT1();
        __syncthreads();
        uint32_t As = sb + (cc & 1) * 3840 * 4;
        uint32_t Bs = As + 2560 * 4;
        #pragma unroll
        for (int ks = 0; ks < 2; ++ks) {
            uint32_t a[2][4], bf[4][2];
            #pragma unroll
            for (int mi = 0; mi < 2; mi++)
                ldsm_x4(a[mi][0], a[mi][1], a[mi][2], a[mi][3],
                        As + aRowOff + (uint32_t)mi * 16 * 80 + (uint32_t)ks * 32);
            ldsm_x4(bf[0][0], bf[0][1], bf[1][0], bf[1][1],
                    Bs + bRowOff + (uint32_t)ks * 32);
            ldsm_x4(bf[2][0], bf[2][1], bf[3][0], bf[3][1],
                    Bs + bRowOff + 16 * 80 + (uint32_t)ks * 32);
            #pragma unroll
            for (int mi = 0; mi < 2; mi++)
                #pragma unroll
                for (int ni = 0; ni < 4; ni++)
                    mma_f16(c[mi][ni], a[mi], bf[ni]);
        }
        __syncthreads();
    }

    __half* Kb = g_Kb + (size_t)b * NN * NN;
    __half* Kw = g_Kw + (size_t)b * NN * NN;
    const float* sq = g_sq + b * NN;
    int i0 = ti * 128 + wm * 32, j0 = tj * 128 + h * 64 + wn * 32;
    bool mir = (ti != tj);

    // hoist sq values into registers
    float sqi[2][2], sqj[4][2];
    #pragma unroll
    for (int mi = 0; mi < 2; mi++)
        #pragma unroll
        for (int rh = 0; rh < 2; rh++)
            sqi[mi][rh] = sq[i0 + mi * 16 + (lane >> 2) + rh * 8];
    #pragma unroll
    for (int ni = 0; ni < 4; ni++)
        #pragma unroll
        for (int rl = 0; rl < 2; rl++)
            sqj[ni][rl] = sq[j0 + ni * 8 + ((lane & 3) << 1) + rl];

    #pragma unroll
    for (int mi = 0; mi < 2; mi++)
        #pragma unroll
        for (int ni = 0; ni < 4; ni++)
            #pragma unroll
            for (int rh = 0; rh < 2; rh++) {
                int i = i0 + mi * 16 + (lane >> 2) + rh * 8;
                int j = j0 + ni * 8 + ((lane & 3) << 1);
                float bkv[2], wkv[2];
                #pragma unroll
                for (int rl = 0; rl < 2; rl++) {
                    float d2 = sqi[mi][rh] + sqj[ni][rl] - 2.f * c[mi][ni][rh * 2 + rl];
                    d2 = fmaxf(d2, 0.f);
                    float t = __expf(d2 * (-1.f / 512.f));
                    bkv[rl] = bk_eval(t);
                    wkv[rl] = wk_eval(t);
                }
                __half2 bh = __floats2half2_rn(bkv[0], bkv[1]);
                __half2 wh = __floats2half2_rn(wkv[0], wkv[1]);
                *(__half2*)(Kb + (size_t)i * NN + j) = bh;
                *(__half2*)(Kw + (size_t)i * NN + j) = wh;
                if (mir) {
                    Kb[(size_t)j * NN + i]       = __low2half(bh);
                    Kb[(size_t)(j + 1) * NN + i] = __high2half(bh);
                    Kw[(size_t)j * NN + i]       = __low2half(wh);
                    Kw[(size_t)(j + 1) * NN + i] = __high2half(wh);
                }
            }
}

// ---------------- kernel: projection P = x @ Wcat (tf32, unchanged) ----------
__global__ __launch_bounds__(256) void k_proj() {
    __shared__ float sm[2 * 3648];
    int c0 = blockIdx.x * 64, byr = blockIdx.y;
    int tid = threadIdx.x, lane = tid & 31, wid = tid >> 5;
    int wm = wid & 1, wn = wid >> 1;
    const float* Xa = g_Xt + (size_t)byr * 128 * DD;
    uint32_t sb = (uint32_t)__cvta_generic_to_shared(sm);

    float c[4][2][4];
    #pragma unroll
    for (int i = 0; i < 4; i++)
        #pragma unroll
        for (int j = 0; j < 2; j++)
            #pragma unroll
            for (int r = 0; r < 4; r++) c[i][j][r] = 0.f;

    {
        uint32_t sA = sb, sB = sb + 2560 * 4;
        #pragma unroll
        for (int it = 0; it < 2; ++it) {
            int id = it * 256 + tid;
            int row = id >> 2, part = (id & 3) << 2;
            cpa16(sA + (row * 20 + part) * 4, Xa + (size_t)row * DD + part);
        }
        int kk = tid >> 4, cq = (tid & 15) << 2;
        cpa16(sB + (kk * 68 + cq) * 4, g_Wcat + (size_t)kk * PC + c0 + cq);
    }
    CP_COMMIT();

    for (int cc = 0; cc < 16; ++cc) {
        if (cc + 1 < 16) {
            int s = (cc + 1) & 1, k0 = (cc + 1) * 16;
            uint32_t sA = sb + (s * 3648) * 4, sB = sA + 2560 * 4;
            #pragma unroll
            for (int it = 0; it < 2; ++it) {
                int id = it * 256 + tid;
                int row = id >> 2, part = (id & 3) << 2;
                cpa16(sA + (row * 20 + part) * 4, Xa + (size_t)row * DD + k0 + part);
            }
            int kk = tid >> 4, cq = (tid & 15) << 2;
            cpa16(sB + (kk * 68 + cq) * 4, g_Wcat + (size_t)(k0 + kk) * PC + c0 + cq);
        }
        CP_COMMIT();
        CP_WAIT1();
        __syncthreads();
        const float* A  = sm + (cc & 1) * 3648;
        const float* Bp = A + 2560;
        #pragma unroll
        for (int ks = 0; ks < 2; ++ks) {
            int kk = ks * 8 + (lane & 3);
            uint32_t a[4][4], bf[2][2];
            #pragma unroll
            for (int mi = 0; mi < 4; mi++) {
                int mr = wm * 64 + mi * 16 + (lane >> 2);
                a[mi][0] = __float_as_uint(A[mr * 20 + kk]);
                a[mi][1] = __float_as_uint(A[(mr + 8) * 20 + kk]);
                a[mi][2] = __float_as_uint(A[mr * 20 + kk + 4]);
                a[mi][3] = __float_as_uint(A[(mr + 8) * 20 + kk + 4]);
            }
            #pragma unroll
            for (int ni = 0; ni < 2; ni++) {
                int nc = wn * 16 + ni * 8 + (lane >> 2);
                bf[ni][0] = __float_as_uint(Bp[kk * 68 + nc]);
                bf[ni][1] = __float_as_uint(Bp[(kk + 4) * 68 + nc]);
            }
            #pragma unroll
            for (int mi = 0; mi < 4; mi++)
                #pragma unroll
                for (int ni = 0; ni < 2; ni++)
                    mma_tf32(c[mi][ni], a[mi], bf[ni]);
        }
        __syncthreads();
    }

    #pragma unroll
    for (int mi = 0; mi < 4; mi++)
        #pragma unroll
        for (int ni = 0; ni < 2; ni++)
            #pragma unroll
            for (int r = 0; r < 4; r++) {
                int row = byr * 128 + wm * 64 + mi * 16 + (lane >> 2) + ((r >> 1) << 3);
                int col = c0 + wn * 16 + ni * 8 + ((lane & 3) << 1) + (r & 1);
                g_P[(size_t)row * PC + col] = c[mi][ni][r];
            }
}

// ---------------- kernel: H2^T fp16 from g_P (smem transpose) ----------------
__global__ __launch_bounds__(256) void k_h2t() {
    __shared__ __half sh[64][72];
    int r0 = blockIdx.x * 64;
    int t = threadIdx.x;
    int r = t >> 2, cq = (t & 3) * 16;
    const float* src = g_P + (size_t)(r0 + r) * PC + 128 + cq;
    #pragma unroll
    for (int q = 0; q < 4; ++q) {
        float4 v = *(const float4*)(src + q * 4);
        sh[r][cq + q * 4 + 0] = __float2half_rn(v.x);
        sh[r][cq + q * 4 + 1] = __float2half_rn(v.y);
        sh[r][cq + q * 4 + 2] = __float2half_rn(v.z);
        sh[r][cq + q * 4 + 3] = __float2half_rn(v.w);
    }
    __syncthreads();
    int c = t >> 2, rq = (t & 3) * 16;
    int b = r0 >> 12, n0 = r0 & (NN - 1);
    __half* dst = g_H2T + ((size_t)b * DOUT + c) * NN + n0 + rq;
    #pragma unroll
    for (int q = 0; q < 16; ++q) dst[q] = sh[rq + q][c];
}

// ---------------- kernel: SpMM fp16, split-K x4, ldmatrix, 3-stage ring ------
// per stage: A 64*20 + B 64*20 u32 = 2560 u32; 3 stages = 30720 B. 4 blocks/SM.
__global__ __launch_bounds__(256, 4) void k_spmm16(int stage) {
    __shared__ uint32_t sm[3 * 2560];
    int rt = blockIdx.x, b = blockIdx.y;
    int type = blockIdx.z >> 2, sp = blockIdx.z & 3;
    int mbase = sp * (NN / 4);
    const __half* Km = (type ? g_Kw : g_Kb) + (size_t)b * NN * NN;
    const __half* Ht;
    float* Out;
    if (stage == 1) {
        Ht = g_H2T + (size_t)b * DOUT * NN;
        float* o4[4] = {g_t0, g_t1, g_t2, g_t3};
        Out = o4[sp] + ((size_t)type * BB + b) * NN * DOUT;
    } else {
        Ht = g_tT + (size_t)(type * BB + b) * DOUT * NN;
        float* o4[4] = {g_g0, g_g1, g_g2, g_g3};
        Out = o4[sp] + ((size_t)type * BB + b) * NN * DOUT;
    }
    int tid = threadIdx.x, lane = tid & 31, wid = tid >> 5;
    int wm = wid & 3, wn = wid >> 2;
    uint32_t sb = (uint32_t)__cvta_generic_to_shared(sm);

    float c[4][4];
    #pragma unroll
    for (int i = 0; i < 4; i++)
        #pragma unroll
        for (int r = 0; r < 4; r++) c[i][r] = 0.f;

    int arow = tid >> 2, apart = tid & 3;
    uint32_t aRowOff = (uint32_t)(wm * 16 + (lane & 15)) * 80 + (uint32_t)(lane >> 4) * 16;
    uint32_t bRowOff = (uint32_t)(wn * 32 + ((lane >> 4) << 3) + (lane & 7)) * 80
                     + (uint32_t)((lane >> 3) & 1) * 16;

    const int NCH = 32;
    // prologue: chunks 0,1 -> stages 0,1
    #pragma unroll
    for (int pc = 0; pc < 2; ++pc) {
        uint32_t sA = sb + pc * 2560 * 4, sB = sA + 1280 * 4;
        int m0 = mbase + pc * 32;
        cpa16(sA + (arow * 20 + apart * 4) * 4, Km + (size_t)(rt * 64 + arow) * NN + m0 + apart * 8);
        cpa16(sB + (arow * 20 + apart * 4) * 4, Ht + (size_t)arow * NN + m0 + apart * 8);
        CP_COMMIT();
    }

    #pragma unroll 1
    for (int cc = 0; cc < NCH; ++cc) {
        CP_WAIT1();
        __syncthreads();
        if (cc + 2 < NCH) {
            int st = (cc + 2) % 3, m0 = mbase + (cc + 2) * 32;
            uint32_t sA = sb + (st * 2560) * 4, sB = sA + 1280 * 4;
            cpa16(sA + (arow * 20 + apart * 4) * 4, Km + (size_t)(rt * 64 + arow) * NN + m0 + apart * 8);
            cpa16(sB + (arow * 20 + apart * 4) * 4, Ht + (size_t)arow * NN + m0 + apart * 8);
        }
        CP_COMMIT();
        uint32_t As = sb + (uint32_t)(cc % 3) * 2560 * 4;
        uint32_t Bs = As + 1280 * 4;
        #pragma unroll
        for (int ks = 0; ks < 2; ++ks) {
            uint32_t a[4], bf[4][2];
            ldsm_x4(a[0], a[1], a[2], a[3], As + aRowOff + (uint32_t)ks * 32);
            ldsm_x4(bf[0][0], bf[0][1], bf[1][0], bf[1][1], Bs + bRowOff + (uint32_t)ks * 32);
            ldsm_x4(bf[2][0], bf[2][1], bf[3][0], bf[3][1], Bs + bRowOff + 16 * 80 + (uint32_t)ks * 32);
            #pragma unroll
            for (int ni = 0; ni < 4; ni++)
                mma_f16(c[ni], a, bf[ni]);
        }
    }

    #pragma unroll
    for (int ni = 0; ni < 4; ni++)
        #pragma unroll
        for (int r = 0; r < 4; r++) {
            int row = rt * 64 + wm * 16 + (lane >> 2) + ((r >> 1) << 3);
            int col = wn * 32 + ni * 8 + ((lane & 3) << 1) + (r & 1);
            Out[(size_t)row * DOUT + col] = c[ni][r];
        }
}

// ---------------- combine stage-1 partials + h1, write fp16 transposed -------
__global__ __launch_bounds__(256) void k_comb1t() {
    __shared__ __half sh[64][72];
    int n0 = blockIdx.x * 64, tb = blockIdx.y;
    int b = tb & 1;
    int t = threadIdx.x;
    int r = t >> 2, cq = (t & 3) * 16;
    size_t base = ((size_t)tb * NN + n0 + r) * DOUT + cq;
    const float* P = g_P + ((size_t)b * NN + n0 + r) * PC + 64 + cq;
    #pragma unroll
    for (int q = 0; q < 4; ++q) {
        float4 v0 = *(const float4*)(g_t0 + base + q * 4);
        float4 v1 = *(const float4*)(g_t1 + base + q * 4);
        float4 v2 = *(const float4*)(g_t2 + base + q * 4);
        float4 v3 = *(const float4*)(g_t3 + base + q * 4);
        float4 vp = *(const float4*)(P + q * 4);
        sh[r][cq + q * 4 + 0] = __float2half_rn((v0.x + v1.x) + (v2.x + v3.x) + vp.x);
        sh[r][cq + q * 4 + 1] = __float2half_rn((v0.y + v1.y) + (v2.y + v3.y) + vp.y);
        sh[r][cq + q * 4 + 2] = __float2half_rn((v0.z + v1.z) + (v2.z + v3.z) + vp.z);
        sh[r][cq + q * 4 + 3] = __float2half_rn((v0.w + v1.w) + (v2.w + v3.w) + vp.w);
    }
    __syncthreads();
    int c = t >> 2, rq = (t & 3) * 16;
    __half* dst = g_tT + ((size_t)tb * DOUT + c) * NN + n0 + rq;
    #pragma unroll
    for (int q = 0; q < 16; ++q) dst[q] = sh[rq + q][c];
}

// ---------------- final epilogue ---------------------------------------------
__global__ void k_final(const float* __restrict__ b_lin, float* __restrict__ out) {
    int idx = blockIdx.x * 256 + threadIdx.x;
    int cidx = idx & 127;
    int n = (idx >> 7) & (NN - 1);
    int b = idx >> 19;
    int half = cidx >> 6, cc = cidx & 63;
    const float* P = g_P + ((size_t)b * NN + n) * PC;
    size_t gi = (((size_t)half * BB + b) * NN + n) * DOUT + cc;
    float g = (g_g0[gi] + g_g1[gi]) + (g_g2[gi] + g_g3[gi]);
    float v = P[cc] + g + P[192 + cidx] + b_lin[cidx];
    out[idx] = fmaxf(v, 0.f);
}

// ---------------- launch -----------------------------------------------------
extern "C" void kernel_launch(void* const* d_in, const int* in_sizes, int n_in,
                              void* d_out, int out_size) {
    const float* x  = (const float*)d_in[0];
    const float* Wk = (const float*)d_in[1];
    const float* Wl = (const float*)d_in[2];
    const float* bl = (const float*)d_in[3];
    float* out = (float*)d_out;

    k_xcvt<<<(BB * NN * DD / 4) / 256, 256>>>(x);
    k_sqnorm<<<BB * NN / 8, 256>>>(x);
    k_wcat<<<(DD * PC + 255) / 256, 256>>>(Wk, Wl);
    k_gram<<<dim3(1056, BB), 256>>>();
    k_proj<<<dim3(PC / 64, (BB * NN) / 128), 256>>>();
    k_h2t<<<(BB * NN) / 64, 256>>>();
    k_spmm16<<<dim3(NN / 64, BB, 8), 256>>>(1);
    k_comb1t<<<dim3(NN / 64, 4), 256>>>();
    k_spmm16<<<dim3(NN / 64, BB, 8), 256>>>(2);
    k_final<<<(BB * NN * 128) / 256, 256>>>(bl, out);
}

// round 16
// speedup vs baseline: 2.1715x; 1.0559x over previous
#include <cuda_runtime.h>
#include <cuda_fp16.h>
#include <cstdint>

#define BB   2
#define NN   4096
#define DD   256
#define PC   320     // 3*64 (Wk) + 128 (W_lin)
#define DOUT 64

// ---------------- scratch ---------------------------------------------------
__device__ __half g_Kb[(size_t)BB * NN * NN];      // fp16 kernel matrices
__device__ __half g_Kw[(size_t)BB * NN * NN];
__device__ float  g_sq[BB * NN];
__device__ __half g_WcatT[(size_t)PC * DD];        // Wcat^T fp16 [c][d]
__device__ __half g_Xh[(size_t)BB * NN * DD];      // fp16 x
__device__ float  g_P[(size_t)BB * NN * PC];       // fp32 x@Wcat
__device__ __half g_H2T[(size_t)BB * DOUT * NN];   // h2^T, fp16 [b][col][row]
__device__ __half g_tT[(size_t)4 * DOUT * NN];     // stage-1^T, fp16 [tb][col][row]
__device__ float  g_t0[(size_t)2 * BB * NN * DOUT];
__device__ float  g_t1[(size_t)2 * BB * NN * DOUT];
__device__ float  g_t2[(size_t)2 * BB * NN * DOUT];
__device__ float  g_t3[(size_t)2 * BB * NN * DOUT];
__device__ float  g_g0[(size_t)2 * BB * NN * DOUT];
__device__ float  g_g1[(size_t)2 * BB * NN * DOUT];
__device__ float  g_g2[(size_t)2 * BB * NN * DOUT];
__device__ float  g_g3[(size_t)2 * BB * NN * DOUT];

// ---------------- helpers ---------------------------------------------------
__device__ __forceinline__ void mma_f16(float c[4], const uint32_t a[4], const uint32_t b[2]) {
    asm volatile(
        "mma.sync.aligned.m16n8k16.row.col.f32.f16.f16.f32 "
        "{%0,%1,%2,%3}, {%4,%5,%6,%7}, {%8,%9}, {%0,%1,%2,%3};\n"
        : "+f"(c[0]), "+f"(c[1]), "+f"(c[2]), "+f"(c[3])
        : "r"(a[0]), "r"(a[1]), "r"(a[2]), "r"(a[3]),
          "r"(b[0]), "r"(b[1]));
}

__device__ __forceinline__ void ldsm_x4(uint32_t& r0, uint32_t& r1, uint32_t& r2, uint32_t& r3,
                                        uint32_t addr) {
    asm volatile("ldmatrix.sync.aligned.m8n8.x4.shared.b16 {%0,%1,%2,%3}, [%4];"
                 : "=r"(r0), "=r"(r1), "=r"(r2), "=r"(r3) : "r"(addr));
}

__device__ __forceinline__ void cpa16(uint32_t dst, const void* src) {
    asm volatile("cp.async.cg.shared.global [%0], [%1], 16;\n" :: "r"(dst), "l"(src));
}
#define CP_COMMIT() asm volatile("cp.async.commit_group;\n" ::: "memory")
#define CP_WAIT1()  asm volatile("cp.async.wait_group 1;\n" ::: "memory")

// Closed-form cubic B-spline on uniform knots {0,.25,.5,.75,1} (== reference).
__device__ __forceinline__ float b3fold(float v) {
    float outer = v * v * v * (1.f / 6.f);
    float inner = (((-3.f * v + 12.f) * v - 12.f) * v + 4.f) * (1.f / 6.f);
    return (v < 1.f) ? outer : inner;
}
__device__ __forceinline__ float bk_eval(float t) {
    float v = 2.f - fabsf(4.f * t - 2.f);
    return b3fold(v);
}
__device__ __forceinline__ float wk_eval(float t) {
    float sg = 8.f * t;
    bool lo = (sg < 4.f);
    float sp = lo ? sg : sg - 4.f;
    float v = 2.f - fabsf(sp - 2.f);
    float r = b3fold(v);
    return lo ? r : -r;
}

// ---------------- tiny prep kernels -----------------------------------------
__global__ void k_xcvt(const float* __restrict__ x) {
    int i = blockIdx.x * 256 + threadIdx.x;
    float4 v = ((const float4*)x)[i];
    __half2 h0 = __floats2half2_rn(v.x, v.y);
    __half2 h1 = __floats2half2_rn(v.z, v.w);
    uint2 ho;
    ho.x = *(uint32_t*)&h0;
    ho.y = *(uint32_t*)&h1;
    ((uint2*)g_Xh)[i] = ho;
}

__global__ void k_sqnorm(const float* __restrict__ x) {
    int row  = blockIdx.x * 8 + (threadIdx.x >> 5);
    int lane = threadIdx.x & 31;
    const float* xr = x + (size_t)row * DD;
    float s = 0.f;
    #pragma unroll
    for (int i = lane; i < DD; i += 32) { float v = xr[i]; s += v * v; }
    #pragma unroll
    for (int o = 16; o; o >>= 1) s += __shfl_xor_sync(0xffffffffu, s, o);
    if (lane == 0) g_sq[row] = s;
}

__global__ void k_wcat(const float* __restrict__ Wk, const float* __restrict__ Wl) {
    int i = blockIdx.x * 256 + threadIdx.x;
    if (i >= DD * PC) return;
    int d = i / PC, cidx = i % PC;
    float v;
    if (cidx < 192) v = Wk[(size_t)(cidx / 64) * DD * 64 + (size_t)d * 64 + (cidx & 63)];
    else            v = Wl[(size_t)d * 128 + (cidx - 192)];
    g_WcatT[(size_t)cidx * DD + d] = __float2half_rn(v);
}

// ---------------- kernel: Gram + spline (fp16, ldmatrix, unchanged R15) ------
__global__ __launch_bounds__(256, 4) void k_gram() {
    __shared__ uint32_t sm[2 * 3840];
    int h   = blockIdx.x & 1;
    int idx = blockIdx.x >> 1;
    int b   = blockIdx.y;
    int tj = (int)((sqrtf(8.f * idx + 1.f) - 1.f) * 0.5f);
    while ((tj + 1) * (tj + 2) / 2 <= idx) ++tj;
    while (tj * (tj + 1) / 2 > idx) --tj;
    int ti = idx - tj * (tj + 1) / 2;

    int tid = threadIdx.x, lane = tid & 31, wid = tid >> 5;
    int wm = wid & 3, wn = wid >> 2;
    const __half* Xa = g_Xh + ((size_t)b * NN + (size_t)ti * 128) * DD;
    const __half* Xb = g_Xh + ((size_t)b * NN + (size_t)tj * 128 + (size_t)h * 64) * DD;
    uint32_t sb = (uint32_t)__cvta_generic_to_shared(sm);

    float c[2][4][4];
    #pragma unroll
    for (int i = 0; i < 2; i++)
        #pragma unroll
        for (int j = 0; j < 4; j++)
            #pragma unroll
            for (int r = 0; r < 4; r++) c[i][j][r] = 0.f;

    int arow_l = tid >> 2,         apart_l = tid & 3;
    int arow_h = (256 + tid) >> 2, apart_h = (256 + tid) & 3;
    int brow   = tid >> 2,         bpart   = tid & 3;

    uint32_t aRowOff = (uint32_t)(wm * 32 + (lane & 15)) * 80 + (uint32_t)(lane >> 4) * 16;
    uint32_t bRowOff = (uint32_t)(wn * 32 + ((lane >> 4) << 3) + (lane & 7)) * 80
                     + (uint32_t)((lane >> 3) & 1) * 16;

    {
        uint32_t sA = sb, sB = sb + 2560 * 4;
        cpa16(sA + (arow_l * 20 + apart_l * 4) * 4, Xa + (size_t)arow_l * DD + apart_l * 8);
        cpa16(sA + (arow_h * 20 + apart_h * 4) * 4, Xa + (size_t)arow_h * DD + apart_h * 8);
        cpa16(sB + (brow * 20 + bpart * 4) * 4, Xb + (size_t)brow * DD + bpart * 8);
    }
    CP_COMMIT();

    for (int cc = 0; cc < 8; ++cc) {
        if (cc + 1 < 8) {
            int s = (cc + 1) & 1, k0 = (cc + 1) * 32;
            uint32_t sA = sb + (s * 3840) * 4, sB = sA + 2560 * 4;
            cpa16(sA + (arow_l * 20 + apart_l * 4) * 4, Xa + (size_t)arow_l * DD + k0 + apart_l * 8);
            cpa16(sA + (arow_h * 20 + apart_h * 4) * 4, Xa + (size_t)arow_h * DD + k0 + apart_h * 8);
            cpa16(sB + (brow * 20 + bpart * 4) * 4, Xb + (size_t)brow * DD + k0 + bpart * 8);
        }
        CP_COMMIT();
        CP_WAIT1();
        __syncthreads();
        uint32_t As = sb + (cc & 1) * 3840 * 4;
        uint32_t Bs = As + 2560 * 4;
        #pragma unroll
        for (int ks = 0; ks < 2; ++ks) {
            uint32_t a[2][4], bf[4][2];
            #pragma unroll
            for (int mi = 0; mi < 2; mi++)
                ldsm_x4(a[mi][0], a[mi][1], a[mi][2], a[mi][3],
                        As + aRowOff + (uint32_t)mi * 16 * 80 + (uint32_t)ks * 32);
            ldsm_x4(bf[0][0], bf[0][1], bf[1][0], bf[1][1],
                    Bs + bRowOff + (uint32_t)ks * 32);
            ldsm_x4(bf[2][0], bf[2][1], bf[3][0], bf[3][1],
                    Bs + bRowOff + 16 * 80 + (uint32_t)ks * 32);
            #pragma unroll
            for (int mi = 0; mi < 2; mi++)
                #pragma unroll
                for (int ni = 0; ni < 4; ni++)
                    mma_f16(c[mi][ni], a[mi], bf[ni]);
        }
        __syncthreads();
    }

    __half* Kb = g_Kb + (size_t)b * NN * NN;
    __half* Kw = g_Kw + (size_t)b * NN * NN;
    const float* sq = g_sq + b * NN;
    int i0 = ti * 128 + wm * 32, j0 = tj * 128 + h * 64 + wn * 32;
    bool mir = (ti != tj);

    float sqi[2][2], sqj[4][2];
    #pragma unroll
    for (int mi = 0; mi < 2; mi++)
        #pragma unroll
        for (int rh = 0; rh < 2; rh++)
            sqi[mi][rh] = sq[i0 + mi * 16 + (lane >> 2) + rh * 8];
    #pragma unroll
    for (int ni = 0; ni < 4; ni++)
        #pragma unroll
        for (int rl = 0; rl < 2; rl++)
            sqj[ni][rl] = sq[j0 + ni * 8 + ((lane & 3) << 1) + rl];

    #pragma unroll
    for (int mi = 0; mi < 2; mi++)
        #pragma unroll
        for (int ni = 0; ni < 4; ni++)
            #pragma unroll
            for (int rh = 0; rh < 2; rh++) {
                int i = i0 + mi * 16 + (lane >> 2) + rh * 8;
                int j = j0 + ni * 8 + ((lane & 3) << 1);
                float bkv[2], wkv[2];
                #pragma unroll
                for (int rl = 0; rl < 2; rl++) {
                    float d2 = sqi[mi][rh] + sqj[ni][rl] - 2.f * c[mi][ni][rh * 2 + rl];
                    d2 = fmaxf(d2, 0.f);
                    float t = __expf(d2 * (-1.f / 512.f));
                    bkv[rl] = bk_eval(t);
                    wkv[rl] = wk_eval(t);
                }
                __half2 bh = __floats2half2_rn(bkv[0], bkv[1]);
                __half2 wh = __floats2half2_rn(wkv[0], wkv[1]);
                *(__half2*)(Kb + (size_t)i * NN + j) = bh;
                *(__half2*)(Kw + (size_t)i * NN + j) = wh;
                if (mir) {
                    Kb[(size_t)j * NN + i]       = __low2half(bh);
                    Kb[(size_t)(j + 1) * NN + i] = __high2half(bh);
                    Kw[(size_t)j * NN + i]       = __low2half(wh);
                    Kw[(size_t)(j + 1) * NN + i] = __high2half(wh);
                }
            }
}

// ---------------- kernel: projection P = x @ Wcat (fp16, ldmatrix, ring) -----
// 64(rows) x 64(cols) tile; 8 warps 4m x 2n; NCH=8 over K=256.
// smem: 3 stages x (A 64x20 + B 64x20) u32 = 30 KB. 4 blocks/SM.
__global__ __launch_bounds__(256, 4) void k_proj16() {
    __shared__ uint32_t sm[3 * 2560];
    int rt = blockIdx.x;             // row tile over BB*NN/64
    int c0 = blockIdx.y * 64;        // col tile
    const __half* Xa = g_Xh + (size_t)rt * 64 * DD;
    int tid = threadIdx.x, lane = tid & 31, wid = tid >> 5;
    int wm = wid & 3, wn = wid >> 2;
    uint32_t sb = (uint32_t)__cvta_generic_to_shared(sm);

    float c[4][4];
    #pragma unroll
    for (int i = 0; i < 4; i++)
        #pragma unroll
        for (int r = 0; r < 4; r++) c[i][r] = 0.f;

    int arow = tid >> 2, apart = tid & 3;
    uint32_t aRowOff = (uint32_t)(wm * 16 + (lane & 15)) * 80 + (uint32_t)(lane >> 4) * 16;
    uint32_t bRowOff = (uint32_t)(wn * 32 + ((lane >> 4) << 3) + (lane & 7)) * 80
                     + (uint32_t)((lane >> 3) & 1) * 16;

    const int NCH = 8;     // 256 / 32
    #pragma unroll
    for (int pc = 0; pc < 2; ++pc) {
        uint32_t sA = sb + pc * 2560 * 4, sB = sA + 1280 * 4;
        int k0 = pc * 32;
        cpa16(sA + (arow * 20 + apart * 4) * 4, Xa + (size_t)arow * DD + k0 + apart * 8);
        cpa16(sB + (arow * 20 + apart * 4) * 4, g_WcatT + (size_t)(c0 + arow) * DD + k0 + apart * 8);
        CP_COMMIT();
    }

    for (int cc = 0; cc < NCH; ++cc) {
        CP_WAIT1();
        __syncthreads();
        if (cc + 2 < NCH) {
            int st = (cc + 2) % 3, k0 = (cc + 2) * 32;
            uint32_t sA = sb + (st * 2560) * 4, sB = sA + 1280 * 4;
            cpa16(sA + (arow * 20 + apart * 4) * 4, Xa + (size_t)arow * DD + k0 + apart * 8);
            cpa16(sB + (arow * 20 + apart * 4) * 4, g_WcatT + (size_t)(c0 + arow) * DD + k0 + apart * 8);
        }
        CP_COMMIT();
        uint32_t As = sb + (uint32_t)(cc % 3) * 2560 * 4;
        uint32_t Bs = As + 1280 * 4;
        #pragma unroll
        for (int ks = 0; ks < 2; ++ks) {
            uint32_t a[4], bf[4][2];
            ldsm_x4(a[0], a[1], a[2], a[3], As + aRowOff + (uint32_t)ks * 32);
            ldsm_x4(bf[0][0], bf[0][1], bf[1][0], bf[1][1], Bs + bRowOff + (uint32_t)ks * 32);
            ldsm_x4(bf[2][0], bf[2][1], bf[3][0], bf[3][1], Bs + bRowOff + 16 * 80 + (uint32_t)ks * 32);
            #pragma unroll
            for (int ni = 0; ni < 4; ni++)
                mma_f16(c[ni], a, bf[ni]);
        }
    }

    #pragma unroll
    for (int ni = 0; ni < 4; ni++)
        #pragma unroll
        for (int r = 0; r < 4; r++) {
            int row = rt * 64 + wm * 16 + (lane >> 2) + ((r >> 1) << 3);
            int col = c0 + wn * 32 + ni * 8 + ((lane & 3) << 1) + (r & 1);
            g_P[(size_t)row * PC + col] = c[ni][r];
        }
}

// ---------------- kernel: H2^T fp16 from g_P (smem transpose) ----------------
__global__ __launch_bounds__(256) void k_h2t() {
    __shared__ __half sh[64][72];
    int r0 = blockIdx.x * 64;
    int t = threadIdx.x;
    int r = t >> 2, cq = (t & 3) * 16;
    const float* src = g_P + (size_t)(r0 + r) * PC + 128 + cq;
    #pragma unroll
    for (int q = 0; q < 4; ++q) {
        float4 v = *(const float4*)(src + q * 4);
        sh[r][cq + q * 4 + 0] = __float2half_rn(v.x);
        sh[r][cq + q * 4 + 1] = __float2half_rn(v.y);
        sh[r][cq + q * 4 + 2] = __float2half_rn(v.z);
        sh[r][cq + q * 4 + 3] = __float2half_rn(v.w);
    }
    __syncthreads();
    int c = t >> 2, rq = (t & 3) * 16;
    int b = r0 >> 12, n0 = r0 & (NN - 1);
    __half* dst = g_H2T + ((size_t)b * DOUT + c) * NN + n0 + rq;
    #pragma unroll
    for (int q = 0; q < 16; ++q) dst[q] = sh[rq + q][c];
}

// ---------------- kernel: SpMM fp16, split-K x4, ldmatrix, 3-stage ring ------
__global__ __launch_bounds__(256, 4) void k_spmm16(int stage) {
    __shared__ uint32_t sm[3 * 2560];
    int rt = blockIdx.x, b = blockIdx.y;
    int type = blockIdx.z >> 2, sp = blockIdx.z & 3;
    int mbase = sp * (NN / 4);
    const __half* Km = (type ? g_Kw : g_Kb) + (size_t)b * NN * NN;
    const __half* Ht;
    float* Out;
    if (stage == 1) {
        Ht = g_H2T + (size_t)b * DOUT * NN;
        float* o4[4] = {g_t0, g_t1, g_t2, g_t3};
        Out = o4[sp] + ((size_t)type * BB + b) * NN * DOUT;
    } else {
        Ht = g_tT + (size_t)(type * BB + b) * DOUT * NN;
        float* o4[4] = {g_g0, g_g1, g_g2, g_g3};
        Out = o4[sp] + ((size_t)type * BB + b) * NN * DOUT;
    }
    int tid = threadIdx.x, lane = tid & 31, wid = tid >> 5;
    int wm = wid & 3, wn = wid >> 2;
    uint32_t sb = (uint32_t)__cvta_generic_to_shared(sm);

    float c[4][4];
    #pragma unroll
    for (int i = 0; i < 4; i++)
        #pragma unroll
        for (int r = 0; r < 4; r++) c[i][r] = 0.f;

    int arow = tid >> 2, apart = tid & 3;
    uint32_t aRowOff = (uint32_t)(wm * 16 + (lane & 15)) * 80 + (uint32_t)(lane >> 4) * 16;
    uint32_t bRowOff = (uint32_t)(wn * 32 + ((lane >> 4) << 3) + (lane & 7)) * 80
                     + (uint32_t)((lane >> 3) & 1) * 16;

    const int NCH = 32;
    #pragma unroll
    for (int pc = 0; pc < 2; ++pc) {
        uint32_t sA = sb + pc * 2560 * 4, sB = sA + 1280 * 4;
        int m0 = mbase + pc * 32;
        cpa16(sA + (arow * 20 + apart * 4) * 4, Km + (size_t)(rt * 64 + arow) * NN + m0 + apart * 8);
        cpa16(sB + (arow * 20 + apart * 4) * 4, Ht + (size_t)arow * NN + m0 + apart * 8);
        CP_COMMIT();
    }

    #pragma unroll 1
    for (int cc = 0; cc < NCH; ++cc) {
        CP_WAIT1();
        __syncthreads();
        if (cc + 2 < NCH) {
            int st = (cc + 2) % 3, m0 = mbase + (cc + 2) * 32;
            uint32_t sA = sb + (st * 2560) * 4, sB = sA + 1280 * 4;
            cpa16(sA + (arow * 20 + apart * 4) * 4, Km + (size_t)(rt * 64 + arow) * NN + m0 + apart * 8);
            cpa16(sB + (arow * 20 + apart * 4) * 4, Ht + (size_t)arow * NN + m0 + apart * 8);
        }
        CP_COMMIT();
        uint32_t As = sb + (uint32_t)(cc % 3) * 2560 * 4;
        uint32_t Bs = As + 1280 * 4;
        #pragma unroll
        for (int ks = 0; ks < 2; ++ks) {
            uint32_t a[4], bf[4][2];
            ldsm_x4(a[0], a[1], a[2], a[3], As + aRowOff + (uint32_t)ks * 32);
            ldsm_x4(bf[0][0], bf[0][1], bf[1][0], bf[1][1], Bs + bRowOff + (uint32_t)ks * 32);
            ldsm_x4(bf[2][0], bf[2][1], bf[3][0], bf[3][1], Bs + bRowOff + 16 * 80 + (uint32_t)ks * 32);
            #pragma unroll
            for (int ni = 0; ni < 4; ni++)
                mma_f16(c[ni], a, bf[ni]);
        }
    }

    #pragma unroll
    for (int ni = 0; ni < 4; ni++)
        #pragma unroll
        for (int r = 0; r < 4; r++) {
            int row = rt * 64 + wm * 16 + (lane >> 2) + ((r >> 1) << 3);
            int col = wn * 32 + ni * 8 + ((lane & 3) << 1) + (r & 1);
            Out[(size_t)row * DOUT + col] = c[ni][r];
        }
}

// ---------------- combine stage-1 partials + h1, write fp16 transposed -------
__global__ __launch_bounds__(256) void k_comb1t() {
    __shared__ __half sh[64][72];
    int n0 = blockIdx.x * 64, tb = blockIdx.y;
    int b = tb & 1;
    int t = threadIdx.x;
    int r = t >> 2, cq = (t & 3) * 16;
    size_t base = ((size_t)tb * NN + n0 + r) * DOUT + cq;
    const float* P = g_P + ((size_t)b * NN + n0 + r) * PC + 64 + cq;
    #pragma unroll
    for (int q = 0; q < 4; ++q) {
        float4 v0 = *(const float4*)(g_t0 + base + q * 4);
        float4 v1 = *(const float4*)(g_t1 + base + q * 4);
        float4 v2 = *(const float4*)(g_t2 + base + q * 4);
        float4 v3 = *(const float4*)(g_t3 + base + q * 4);
        float4 vp = *(const float4*)(P + q * 4);
        sh[r][cq + q * 4 + 0] = __float2half_rn((v0.x + v1.x) + (v2.x + v3.x) + vp.x);
        sh[r][cq + q * 4 + 1] = __float2half_rn((v0.y + v1.y) + (v2.y + v3.y) + vp.y);
        sh[r][cq + q * 4 + 2] = __float2half_rn((v0.z + v1.z) + (v2.z + v3.z) + vp.z);
        sh[r][cq + q * 4 + 3] = __float2half_rn((v0.w + v1.w) + (v2.w + v3.w) + vp.w);
    }
    __syncthreads();
    int c = t >> 2, rq = (t & 3) * 16;
    __half* dst = g_tT + ((size_t)tb * DOUT + c) * NN + n0 + rq;
    #pragma unroll
    for (int q = 0; q < 16; ++q) dst[q] = sh[rq + q][c];
}

// ---------------- final epilogue ---------------------------------------------
__global__ void k_final(const float* __restrict__ b_lin, float* __restrict__ out) {
    int idx = blockIdx.x * 256 + threadIdx.x;
    int cidx = idx & 127;
    int n = (idx >> 7) & (NN - 1);
    int b = idx >> 19;
    int half = cidx >> 6, cc = cidx & 63;
    const float* P = g_P + ((size_t)b * NN + n) * PC;
    size_t gi = (((size_t)half * BB + b) * NN + n) * DOUT + cc;
    float g = (g_g0[gi] + g_g1[gi]) + (g_g2[gi] + g_g3[gi]);
    float v = P[cc] + g + P[192 + cidx] + b_lin[cidx];
    out[idx] = fmaxf(v, 0.f);
}

// ---------------- launch -----------------------------------------------------
extern "C" void kernel_launch(void* const* d_in, const int* in_sizes, int n_in,
                              void* d_out, int out_size) {
    const float* x  = (const float*)d_in[0];
    const float* Wk = (const float*)d_in[1];
    const float* Wl = (const float*)d_in[2];
    const float* bl = (const float*)d_in[3];
    float* out = (float*)d_out;

    k_xcvt<<<(BB * NN * DD / 4) / 256, 256>>>(x);
    k_sqnorm<<<BB * NN / 8, 256>>>(x);
    k_wcat<<<(DD * PC + 255) / 256, 256>>>(Wk, Wl);
    k_gram<<<dim3(1056, BB), 256>>>();
    k_proj16<<<dim3((BB * NN) / 64, PC / 64), 256>>>();
    k_h2t<<<(BB * NN) / 64, 256>>>();
    k_spmm16<<<dim3(NN / 64, BB, 8), 256>>>(1);
    k_comb1t<<<dim3(NN / 64, 4), 256>>>();
    k_spmm16<<<dim3(NN / 64, BB, 8), 256>>>(2);
    k_final<<<(BB * NN * 128) / 256, 256>>>(bl, out);
}